// round 10
// baseline (speedup 1.0000x reference)
#include <cuda_runtime.h>
#include <cuda_fp16.h>
#include <math.h>
#include <stdint.h>

#define NA 50000
#define NB 50000
#define NEDGE 1000000
#define LPRED 100000

// ---------------- device scratch pools ----------------
#define OFF_XAH   0u
#define OFF_XAL   6400000u
#define OFF_XBH   12800000u
#define OFF_XBL   19200000u
#define OFF_HAB   25600000u
#define OFF_HBA   38400000u
#define OFF_SSAB  51200000u
#define OFF_SSBA  51250000u
#define OFF_DDAB  51300000u
#define OFF_DDBA  51350000u
#define OFF_SV    51400000u             // 6*256 dv vectors (padded 2048)
#define OFF_SUM16 51402048u
#define OFF_WTABH 51402064u
#define OFF_WTABL 51434832u
#define OFF_WTBAH 51467600u
#define OFF_WTBAL 51500368u
#define FPOOL_N   51533136u

#define IOFF_RP2   0u
#define IOFF_CNT2  100001u
#define IOFF_FILL2 200001u
#define IOFF_SRT   300001u
#define IOFF_BSUM  2300001u
#define IPOOL_N    2300129u

static __device__ float g_fpool[FPOOL_N];
static __device__ int   g_ipool[IPOOL_N];

// ---------------- fp16 hi/lo split helpers ----------------
__device__ __forceinline__ void split2(float x, float y, __half2* ph, __half2* pl) {
    float hx = __uint_as_float(__float_as_uint(x) & 0xFFFFE000u);
    float hy = __uint_as_float(__float_as_uint(y) & 0xFFFFE000u);
    *ph = __halves2half2(__float2half_rn(hx), __float2half_rn(hy));
    *pl = __halves2half2(__float2half_rn(x - hx), __float2half_rn(y - hy));
}

__device__ __forceinline__ void split_store4(float4 v, __half* ph, __half* pl) {
    __half2 h01, l01, h23, l23;
    split2(v.x, v.y, &h01, &l01);
    split2(v.z, v.w, &h23, &l23);
    *(__half2*)(ph)     = h01;
    *(__half2*)(ph + 2) = h23;
    *(__half2*)(pl)     = l01;
    *(__half2*)(pl + 2) = l23;
}

#define MMA_F16(cc, aa, bb)                                                         \
    asm volatile(                                                                   \
        "mma.sync.aligned.m16n8k16.row.col.f32.f16.f16.f32 "                        \
        "{%0,%1,%2,%3},{%4,%5,%6,%7},{%8,%9},{%0,%1,%2,%3};\n"                      \
        : "+f"((cc)[0]), "+f"((cc)[1]), "+f"((cc)[2]), "+f"((cc)[3])                \
        : "r"((aa)[0]), "r"((aa)[1]), "r"((aa)[2]), "r"((aa)[3]),                   \
          "r"((bb)[0]), "r"((bb)[1]))

// ---------------- merged HMMA GEMM (R7 staging: direct LDG.128 + STS, single buffer) ----------------
// blockIdx.z selects direction. C(half)[M,256] = A[M,K] @ Bt[256,K]^T,
// fp16 hi/lo 3-term; fused ssOut[r] += sum_c C[r,c]*sv[c].
__global__ void __launch_bounds__(256) gemm2_kernel(
    const __half* __restrict__ A0h, const __half* __restrict__ A0l,
    const __half* __restrict__ B0h, const __half* __restrict__ B0l,
    __half* __restrict__ C0, const float* __restrict__ sv0, float* __restrict__ ss0,
    const __half* __restrict__ A1h, const __half* __restrict__ A1l,
    const __half* __restrict__ B1h, const __half* __restrict__ B1l,
    __half* __restrict__ C1, const float* __restrict__ sv1, float* __restrict__ ss1,
    int M, int K) {
    __shared__ __half Ah[128][40], Al[128][40], Bh[128][40], Bl[128][40];
    __shared__ float ssred[128];

    const __half* Ahg = blockIdx.z ? A1h : A0h;
    const __half* Alg = blockIdx.z ? A1l : A0l;
    const __half* Bhg = blockIdx.z ? B1h : B0h;
    const __half* Blg = blockIdx.z ? B1l : B0l;
    __half* C = blockIdx.z ? C1 : C0;
    const float* sv = blockIdx.z ? sv1 : sv0;
    float* ssOut = blockIdx.z ? ss1 : ss0;

    int tid = threadIdx.x;
    int warp = tid >> 5, lane = tid & 31;
    int g = lane >> 2, tg = lane & 3;
    int wm = warp >> 2, wn = warp & 3;
    int bm = blockIdx.x * 128, bn = blockIdx.y * 128;

    float c[4][4][4] = {};

    for (int k0 = 0; k0 < K; k0 += 32) {
        // stage (pure copy): 512 uint4 per array, 2 per thread per array
#pragma unroll
        for (int j = 0; j < 2; j++) {
            int idx = tid + j * 256;
            int row = idx >> 2, q = (idx & 3) * 8;
            uint4 vh = make_uint4(0, 0, 0, 0), vl = make_uint4(0, 0, 0, 0);
            int gr = bm + row;
            if (gr < M) {
                vh = *(const uint4*)(Ahg + (size_t)gr * K + k0 + q);
                vl = *(const uint4*)(Alg + (size_t)gr * K + k0 + q);
            }
            *(uint4*)&Ah[row][q] = vh;
            *(uint4*)&Al[row][q] = vl;
            uint4 wh = *(const uint4*)(Bhg + (size_t)(bn + row) * K + k0 + q);
            uint4 wl = *(const uint4*)(Blg + (size_t)(bn + row) * K + k0 + q);
            *(uint4*)&Bh[row][q] = wh;
            *(uint4*)&Bl[row][q] = wl;
        }
        __syncthreads();

#pragma unroll
        for (int ks = 0; ks < 2; ks++) {
            int kc = ks * 16 + tg * 2;
            unsigned ah[4][4], al[4][4], bh[4][2], bl[4][2];
#pragma unroll
            for (int mt = 0; mt < 4; mt++) {
                int r = wm * 64 + mt * 16 + g;
                ah[mt][0] = *(const unsigned*)&Ah[r][kc];
                ah[mt][1] = *(const unsigned*)&Ah[r + 8][kc];
                ah[mt][2] = *(const unsigned*)&Ah[r][kc + 8];
                ah[mt][3] = *(const unsigned*)&Ah[r + 8][kc + 8];
                al[mt][0] = *(const unsigned*)&Al[r][kc];
                al[mt][1] = *(const unsigned*)&Al[r + 8][kc];
                al[mt][2] = *(const unsigned*)&Al[r][kc + 8];
                al[mt][3] = *(const unsigned*)&Al[r + 8][kc + 8];
            }
#pragma unroll
            for (int nt = 0; nt < 4; nt++) {
                int n = wn * 32 + nt * 8 + g;
                bh[nt][0] = *(const unsigned*)&Bh[n][kc];
                bh[nt][1] = *(const unsigned*)&Bh[n][kc + 8];
                bl[nt][0] = *(const unsigned*)&Bl[n][kc];
                bl[nt][1] = *(const unsigned*)&Bl[n][kc + 8];
            }
#pragma unroll
            for (int mt = 0; mt < 4; mt++)
#pragma unroll
                for (int nt = 0; nt < 4; nt++) {
                    MMA_F16(c[mt][nt], ah[mt], bl[nt]);
                    MMA_F16(c[mt][nt], al[mt], bh[nt]);
                    MMA_F16(c[mt][nt], ah[mt], bh[nt]);
                }
        }
        __syncthreads();
    }

    // ss: per-row dot of C with sv
    if (tid < 128) ssred[tid] = 0.f;
    __syncthreads();
#pragma unroll
    for (int mt = 0; mt < 4; mt++) {
        float p0 = 0.f, p1 = 0.f;
#pragma unroll
        for (int nt = 0; nt < 4; nt++) {
            int col0 = bn + wn * 32 + nt * 8 + tg * 2;
            float2 sva = __ldg((const float2*)sv + (col0 >> 1));
            p0 += c[mt][nt][0] * sva.x + c[mt][nt][1] * sva.y;
            p1 += c[mt][nt][2] * sva.x + c[mt][nt][3] * sva.y;
        }
        p0 += __shfl_xor_sync(0xffffffffu, p0, 1);
        p0 += __shfl_xor_sync(0xffffffffu, p0, 2);
        p1 += __shfl_xor_sync(0xffffffffu, p1, 1);
        p1 += __shfl_xor_sync(0xffffffffu, p1, 2);
        if (tg == 0) {
            int rl = wm * 64 + mt * 16 + g;
            atomicAdd(&ssred[rl], p0);
            atomicAdd(&ssred[rl + 8], p1);
        }
    }
    __syncthreads();
    if (tid < 128) {
        int row = bm + tid;
        if (row < M) atomicAdd(ssOut + row, ssred[tid]);
    }

    // C store (fp16)
#pragma unroll
    for (int mt = 0; mt < 4; mt++) {
        int r0 = bm + wm * 64 + mt * 16 + g;
#pragma unroll
        for (int nt = 0; nt < 4; nt++) {
            int cc = bn + wn * 32 + nt * 8 + tg * 2;
            __half2 p0 = __floats2half2_rn(c[mt][nt][0], c[mt][nt][1]);
            __half2 p1 = __floats2half2_rn(c[mt][nt][2], c[mt][nt][3]);
            if (r0 < M)     *(__half2*)(C + (size_t)r0 * 256 + cc) = p0;
            if (r0 + 8 < M) *(__half2*)(C + (size_t)(r0 + 8) * 256 + cc) = p1;
        }
    }
}

// ---------------- transpose + split weights ----------------
__global__ void transpose2split_kernel(const float* __restrict__ W0,
                                       __half* __restrict__ T0h, __half* __restrict__ T0l,
                                       const float* __restrict__ W1,
                                       __half* __restrict__ T1h, __half* __restrict__ T1l,
                                       int K, int N) {
    __shared__ float t[32][33];
    const float* W = blockIdx.z ? W1 : W0;
    __half* Th = blockIdx.z ? T1h : T0h;
    __half* Tl = blockIdx.z ? T1l : T0l;
    int n0 = blockIdx.x * 32, k0 = blockIdx.y * 32;
#pragma unroll
    for (int i = 0; i < 4; i++) {
        int k = k0 + threadIdx.y + i * 8;
        t[threadIdx.y + i * 8][threadIdx.x] = W[(size_t)k * N + n0 + threadIdx.x];
    }
    __syncthreads();
#pragma unroll
    for (int i = 0; i < 4; i++) {
        int n = n0 + threadIdx.y + i * 8;
        float v = t[threadIdx.x][threadIdx.y + i * 8];
        float hv = __uint_as_float(__float_as_uint(v) & 0xFFFFE000u);
        Th[(size_t)n * K + k0 + threadIdx.x] = __float2half_rn(hv);
        Tl[(size_t)n * K + k0 + threadIdx.x] = __float2half_rn(v - hv);
    }
}

// ---------------- layer-1 X split (K=128) + dd dot ----------------
__global__ void splitX_kernel(const float* __restrict__ X,
                              __half* __restrict__ Xh, __half* __restrict__ Xl,
                              const float* __restrict__ dv, float* __restrict__ dd,
                              int M) {
    int w = (blockIdx.x * blockDim.x + threadIdx.x) >> 5;
    int lane = threadIdx.x & 31;
    if (w >= M) return;
    float4 v = *(const float4*)(X + (size_t)w * 128 + lane * 4);
    float4 dvv = __ldg((const float4*)dv + lane);
    float acc = v.x * dvv.x + v.y * dvv.y + v.z * dvv.z + v.w * dvv.w;
    split_store4(v, Xh + (size_t)w * 128 + lane * 4, Xl + (size_t)w * 128 + lane * 4);
#pragma unroll
    for (int o = 16; o; o >>= 1) acc += __shfl_xor_sync(0xffffffffu, acc, o);
    if (lane == 0) dd[w] = acc;
}

// ---------------- small-N GEMM (layer 3), merged both directions ----------------
__global__ void __launch_bounds__(512) gemm_n16_2_kernel(
    const __half* __restrict__ X0h, const __half* __restrict__ X0l,
    const float* __restrict__ W0f, float* __restrict__ H0,
    const float* __restrict__ sv0, float* __restrict__ ss0,
    const __half* __restrict__ X1h, const __half* __restrict__ X1l,
    const float* __restrict__ W1f, float* __restrict__ H1,
    const float* __restrict__ sv1, float* __restrict__ ss1, int M) {
    const __half* Xh = blockIdx.y ? X1h : X0h;
    const __half* Xl = blockIdx.y ? X1l : X0l;
    const float* W = blockIdx.y ? W1f : W0f;
    float* H = blockIdx.y ? H1 : H0;
    const float* sv = blockIdx.y ? sv1 : sv0;
    float* ssOut = blockIdx.y ? ss1 : ss0;

    __shared__ float Ws[256 * 16];
    __shared__ float Xs[32 * 256];
    int tid = threadIdx.x;
    int row0 = blockIdx.x * 32;
    for (int i = tid; i < 256 * 16 / 4; i += 512)
        *(float4*)&Ws[i * 4] = *(const float4*)(W + i * 4);
#pragma unroll
    for (int i = 0; i < 4; i++) {
        int lin = tid + i * 512;
        int r = lin / 64;
        int c4 = lin % 64;
        float4 v = make_float4(0.f, 0.f, 0.f, 0.f);
        if (row0 + r < M) {
            uint2 vh = *(const uint2*)(Xh + (size_t)(row0 + r) * 256 + c4 * 4);
            uint2 vl = *(const uint2*)(Xl + (size_t)(row0 + r) * 256 + c4 * 4);
            const __half2* ph = (const __half2*)&vh;
            const __half2* pl = (const __half2*)&vl;
            float2 a0 = __half22float2(ph[0]), a1 = __half22float2(ph[1]);
            float2 b0 = __half22float2(pl[0]), b1 = __half22float2(pl[1]);
            v = make_float4(a0.x + b0.x, a0.y + b0.y, a1.x + b1.x, a1.y + b1.y);
        }
        *(float4*)&Xs[r * 256 + c4 * 4] = v;
    }
    __syncthreads();

    int r = tid / 16, c = tid % 16;
    float acc = 0.f;
#pragma unroll 8
    for (int k = 0; k < 256; k++) acc += Xs[r * 256 + k] * Ws[k * 16 + c];

    float sp = acc * __ldg(sv + c);
    sp += __shfl_xor_sync(0xffffffffu, sp, 1);
    sp += __shfl_xor_sync(0xffffffffu, sp, 2);
    sp += __shfl_xor_sync(0xffffffffu, sp, 4);
    sp += __shfl_xor_sync(0xffffffffu, sp, 8);
    if (row0 + r < M) {
        if ((tid & 15) == 0) ssOut[row0 + r] = sp;
        H[(size_t)(row0 + r) * 16 + c] = acc;
    }
}

// ---------------- fused dual W@a ----------------
__global__ void wv2_kernel(const float* __restrict__ W0, const float* __restrict__ a0,
                           float* __restrict__ o0,
                           const float* __restrict__ W1, const float* __restrict__ a1,
                           float* __restrict__ o1, int Fin, int Fout) {
    const float* W = blockIdx.y ? W1 : W0;
    const float* a = blockIdx.y ? a1 : a0;
    float* o = blockIdx.y ? o1 : o0;
    int w = (blockIdx.x * blockDim.x + threadIdx.x) >> 5;
    int lane = threadIdx.x & 31;
    if (w >= Fin) return;
    float s = 0.f;
    for (int j = lane; j < Fout; j += 32) s += W[(size_t)w * Fout + j] * a[j];
    for (int o2 = 16; o2; o2 >>= 1) s += __shfl_down_sync(0xffffffffu, s, o2);
    if (lane == 0) o[w] = s;
}

// ---------------- concatenated 2-direction CSR build ----------------
__global__ void hist2_kernel(const int* __restrict__ eab, const int* __restrict__ eba,
                             int* __restrict__ cnt) {
    int e = blockIdx.x * blockDim.x + threadIdx.x;
    if (e < NEDGE) atomicAdd(&cnt[eab[NEDGE + e]], 1);
    else if (e < 2 * NEDGE) atomicAdd(&cnt[NB + eba[NEDGE + e - NEDGE]], 1);
}

__global__ void scan1_kernel(const int* __restrict__ cnt, int* __restrict__ rowptr,
                             int* __restrict__ bsum, int n) {
    __shared__ int sh[1024];
    int i = blockIdx.x * 1024 + threadIdx.x;
    int v = (i < n) ? cnt[i] : 0;
    sh[threadIdx.x] = v;
    __syncthreads();
    for (int off = 1; off < 1024; off <<= 1) {
        int t = (threadIdx.x >= off) ? sh[threadIdx.x - off] : 0;
        __syncthreads();
        sh[threadIdx.x] += t;
        __syncthreads();
    }
    if (i < n) rowptr[i + 1] = sh[threadIdx.x];
    if (threadIdx.x == 1023) bsum[blockIdx.x] = sh[1023];
}

__global__ void scan2_kernel(int* __restrict__ bsum, int nb) {
    __shared__ int sh[128];
    int t = threadIdx.x;
    int v = (t < nb) ? bsum[t] : 0;
    sh[t] = v;
    __syncthreads();
    for (int off = 1; off < 128; off <<= 1) {
        int u = (t >= off) ? sh[t - off] : 0;
        __syncthreads();
        sh[t] += u;
        __syncthreads();
    }
    if (t < nb) bsum[t] = sh[t] - v;
}

__global__ void scan3_kernel(int* __restrict__ rowptr, const int* __restrict__ bsum, int n) {
    int i = blockIdx.x * 1024 + threadIdx.x;
    if (i < n) rowptr[i + 1] += bsum[blockIdx.x];
    if (i == 0) rowptr[0] = 0;
}

__global__ void scatter2_kernel(const int* __restrict__ eab, const int* __restrict__ eba,
                                const int* __restrict__ rowptr, int* __restrict__ fill,
                                int* __restrict__ sorted) {
    int e = blockIdx.x * blockDim.x + threadIdx.x;
    int s, seg;
    if (e < NEDGE) { s = eab[e]; seg = eab[NEDGE + e]; }
    else if (e < 2 * NEDGE) { int e2 = e - NEDGE; s = eba[e2]; seg = NB + eba[NEDGE + e2]; }
    else return;
    int p = rowptr[seg] + atomicAdd(&fill[seg], 1);
    sorted[p] = s;
}

// ---------------- merged fused GAT (FOUT=256), both directions in one launch ----------------
__global__ void __launch_bounds__(256) gat256h2_kernel(
    const int* __restrict__ rowptr, const int* __restrict__ ssrc,
    const float* __restrict__ ss0, const float* __restrict__ dd0,
    const __half* __restrict__ H0, const float* __restrict__ b0,
    __half* __restrict__ Xh0, __half* __restrict__ Xl0,
    const float* __restrict__ dv0, float* __restrict__ ddn0,
    const float* __restrict__ ss1, const float* __restrict__ dd1,
    const __half* __restrict__ H1, const float* __restrict__ b1,
    __half* __restrict__ Xh1, __half* __restrict__ Xl1,
    const float* __restrict__ dv1, float* __restrict__ ddn1) {
    int w = (blockIdx.x * blockDim.x + threadIdx.x) >> 5;
    int lane = threadIdx.x & 31;
    if (w >= NA + NB) return;
    bool d1 = (w >= NB);
    int n = d1 ? (w - NB) : w;
    const float* ss = d1 ? ss1 : ss0;
    const float* ddp = d1 ? dd1 : dd0;
    const __half* H = d1 ? H1 : H0;
    const float* bias = d1 ? b1 : b0;
    __half* Xh = d1 ? Xh1 : Xh0;
    __half* Xl = d1 ? Xl1 : Xl0;
    const float* dvn = d1 ? dv1 : dv0;
    float* ddn = d1 ? ddn1 : ddn0;

    int b0i = rowptr[w], b1i = rowptr[w + 1];
    float ddv = ddp[n];

    float mx = __int_as_float(0xff800000);
    for (int i = b0i + lane; i < b1i; i += 32) {
        float v = __ldg(ss + ssrc[i]) + ddv;
        v = v > 0.f ? v : 0.2f * v;
        mx = fmaxf(mx, v);
    }
#pragma unroll
    for (int o = 16; o; o >>= 1) mx = fmaxf(mx, __shfl_xor_sync(0xffffffffu, mx, o));

    float acc[8] = {};
    float sum = 0.f;
    for (int base = b0i; base < b1i; base += 32) {
        int i = base + lane;
        float wgt = 0.f;
        int s = 0;
        if (i < b1i) {
            s = ssrc[i];
            float v = __ldg(ss + s) + ddv;
            v = v > 0.f ? v : 0.2f * v;
            wgt = __expf(v - mx);
        }
        sum += wgt;
        int nn = min(32, b1i - base);
        for (int t = 0; t < nn; t++) {
            float wt = __shfl_sync(0xffffffffu, wgt, t);
            int st = __shfl_sync(0xffffffffu, s, t);
            uint4 u = __ldg((const uint4*)(H + (size_t)st * 256) + lane);
            const __half2* hh = (const __half2*)&u;
#pragma unroll
            for (int j = 0; j < 4; j++) {
                float2 f = __half22float2(hh[j]);
                acc[2 * j]     += wt * f.x;
                acc[2 * j + 1] += wt * f.y;
            }
        }
    }
#pragma unroll
    for (int o = 16; o; o >>= 1) sum += __shfl_xor_sync(0xffffffffu, sum, o);
    float inv = 1.f / (sum + 1e-16f);

    float4 bb0 = __ldg((const float4*)bias + lane * 2);
    float4 bb1 = __ldg((const float4*)bias + lane * 2 + 1);
    float4 o0, o1;
    o0.x = fmaxf(acc[0] * inv + bb0.x, 0.f); o0.y = fmaxf(acc[1] * inv + bb0.y, 0.f);
    o0.z = fmaxf(acc[2] * inv + bb0.z, 0.f); o0.w = fmaxf(acc[3] * inv + bb0.w, 0.f);
    o1.x = fmaxf(acc[4] * inv + bb1.x, 0.f); o1.y = fmaxf(acc[5] * inv + bb1.y, 0.f);
    o1.z = fmaxf(acc[6] * inv + bb1.z, 0.f); o1.w = fmaxf(acc[7] * inv + bb1.w, 0.f);

    union U4 { __half2 h2[4]; uint4 u; };
    U4 uh, ul;
    split2(o0.x, o0.y, &uh.h2[0], &ul.h2[0]);
    split2(o0.z, o0.w, &uh.h2[1], &ul.h2[1]);
    split2(o1.x, o1.y, &uh.h2[2], &ul.h2[2]);
    split2(o1.z, o1.w, &uh.h2[3], &ul.h2[3]);
    *(uint4*)(Xh + (size_t)n * 256 + lane * 8) = uh.u;
    *(uint4*)(Xl + (size_t)n * 256 + lane * 8) = ul.u;

    float4 dva = __ldg((const float4*)dvn + lane * 2);
    float4 dvb = __ldg((const float4*)dvn + lane * 2 + 1);
    float dq = o0.x * dva.x + o0.y * dva.y + o0.z * dva.z + o0.w * dva.w
             + o1.x * dvb.x + o1.y * dvb.y + o1.z * dvb.z + o1.w * dvb.w;
#pragma unroll
    for (int o = 16; o; o >>= 1) dq += __shfl_xor_sync(0xffffffffu, dq, o);
    if (lane == 0) ddn[n] = dq;
}

// ---------------- merged fused GAT (FOUT=16, final layer) ----------------
__global__ void __launch_bounds__(256) gat16_2_kernel(
    const int* __restrict__ rowptr, const int* __restrict__ ssrc,
    const float* __restrict__ ss0, const float* __restrict__ dd0,
    const float* __restrict__ H0, const float* __restrict__ b0,
    float* __restrict__ out0,
    const float* __restrict__ ss1, const float* __restrict__ dd1,
    const float* __restrict__ H1, const float* __restrict__ b1,
    float* __restrict__ out1) {
    int w = (blockIdx.x * blockDim.x + threadIdx.x) >> 5;
    int lane = threadIdx.x & 31;
    if (w >= NA + NB) return;
    bool d1 = (w >= NB);
    int n = d1 ? (w - NB) : w;
    const float* ss = d1 ? ss1 : ss0;
    const float* ddp = d1 ? dd1 : dd0;
    const float* H = d1 ? H1 : H0;
    const float* bias = d1 ? b1 : b0;
    float* out = d1 ? out1 : out0;

    int b0i = rowptr[w], b1i = rowptr[w + 1];
    float ddv = ddp[n];
    int half = lane >> 4, fl = lane & 15;

    float mx = __int_as_float(0xff800000);
    for (int i = b0i + lane; i < b1i; i += 32) {
        float v = __ldg(ss + ssrc[i]) + ddv;
        v = v > 0.f ? v : 0.2f * v;
        mx = fmaxf(mx, v);
    }
#pragma unroll
    for (int o = 16; o; o >>= 1) mx = fmaxf(mx, __shfl_xor_sync(0xffffffffu, mx, o));

    float acc = 0.f;
    float sum = 0.f;
    for (int base = b0i; base < b1i; base += 32) {
        int i = base + lane;
        float wgt = 0.f;
        int s = 0;
        if (i < b1i) {
            s = ssrc[i];
            float v = __ldg(ss + s) + ddv;
            v = v > 0.f ? v : 0.2f * v;
            wgt = __expf(v - mx);
        }
        sum += wgt;
        int nn = min(32, b1i - base);
        for (int t = 0; t < nn; t += 2) {
            int tt = t + half;
            float wt = __shfl_sync(0xffffffffu, wgt, tt);
            int st = __shfl_sync(0xffffffffu, s, tt);
            if (tt < nn) acc += wt * __ldg(H + (size_t)st * 16 + fl);
        }
    }
#pragma unroll
    for (int o = 16; o; o >>= 1) sum += __shfl_xor_sync(0xffffffffu, sum, o);
    acc += __shfl_xor_sync(0xffffffffu, acc, 16);
    float inv = 1.f / (sum + 1e-16f);
    if (lane < 16)
        out[(size_t)n * 16 + lane] = acc * inv + __ldg(bias + lane);
}

// ---------------- readout ----------------
__global__ void sumrows16_kernel(const float* __restrict__ xb, const int* __restrict__ dstidx,
                                 float* __restrict__ out16, int L) {
    __shared__ float sh[16];
    if (threadIdx.x < 16) sh[threadIdx.x] = 0.f;
    __syncthreads();
    float loc[16];
#pragma unroll
    for (int k = 0; k < 16; k++) loc[k] = 0.f;
    for (int t = blockIdx.x * blockDim.x + threadIdx.x; t < L; t += gridDim.x * blockDim.x) {
        const float* row = xb + (size_t)dstidx[t] * 16;
#pragma unroll
        for (int k = 0; k < 16; k++) loc[k] += row[k];
    }
#pragma unroll
    for (int k = 0; k < 16; k++) atomicAdd(&sh[k], loc[k]);
    __syncthreads();
    if (threadIdx.x < 16) atomicAdd(&out16[threadIdx.x], sh[threadIdx.x]);
}

__global__ void pred_kernel(const float* __restrict__ xa, const int* __restrict__ srcidx,
                            const float* __restrict__ sum16, float* __restrict__ pred, int L) {
    int t = blockIdx.x * blockDim.x + threadIdx.x;
    if (t >= L) return;
    const float* row = xa + (size_t)srcidx[t] * 16;
    float s = 0.f;
#pragma unroll
    for (int k = 0; k < 16; k++) s += row[k] * __ldg(sum16 + k);
    pred[t] = s;
}

// ---------------- host orchestration ----------------
static inline int cdiv(int a, int b) { return (a + b - 1) / b; }

extern "C" void kernel_launch(void* const* d_in, const int* in_sizes, int n_in,
                              void* d_out, int out_size) {
    const float* xAin = (const float*)d_in[0];
    const float* xBin = (const float*)d_in[1];
    const int* ei_ab = (const int*)d_in[2];
    const int* ei_ba = (const int*)d_in[3];
    const int* srcI = (const int*)d_in[4];
    const int* dstI = (const int*)d_in[5];

    const float* Wab[3]  = {(const float*)d_in[6],  (const float*)d_in[14], (const float*)d_in[22]};
    const float* asab[3] = {(const float*)d_in[7],  (const float*)d_in[15], (const float*)d_in[23]};
    const float* adab[3] = {(const float*)d_in[8],  (const float*)d_in[16], (const float*)d_in[24]};
    const float* bab[3]  = {(const float*)d_in[9],  (const float*)d_in[17], (const float*)d_in[25]};
    const float* Wba[3]  = {(const float*)d_in[10], (const float*)d_in[18], (const float*)d_in[26]};
    const float* asba[3] = {(const float*)d_in[11], (const float*)d_in[19], (const float*)d_in[27]};
    const float* adba[3] = {(const float*)d_in[12], (const float*)d_in[20], (const float*)d_in[28]};
    const float* bba[3]  = {(const float*)d_in[13], (const float*)d_in[21], (const float*)d_in[29]};

    float* out = (float*)d_out;
    float* pred = out;
    float* xaOut = out + LPRED;
    float* xbOut = xaOut + (size_t)NA * 16;

    float* F = nullptr;
    int* I = nullptr;
    cudaGetSymbolAddress((void**)&F, g_fpool);
    cudaGetSymbolAddress((void**)&I, g_ipool);

    __half* XAH = (__half*)(F + OFF_XAH);
    __half* XAL = (__half*)(F + OFF_XAL);
    __half* XBH = (__half*)(F + OFF_XBH);
    __half* XBL = (__half*)(F + OFF_XBL);
    float* HABf = F + OFF_HAB;
    float* HBAf = F + OFF_HBA;
    __half* HABh = (__half*)(F + OFF_HAB);
    __half* HBAh = (__half*)(F + OFF_HBA);
    float* SSAB = F + OFF_SSAB;
    float* SSBA = F + OFF_SSBA;
    float* DDAB = F + OFF_DDAB;
    float* DDBA = F + OFF_DDBA;
    float* SV = F + OFF_SV;
    float* SUM16 = F + OFF_SUM16;
    __half* WTABH = (__half*)(F + OFF_WTABH);
    __half* WTABL = (__half*)(F + OFF_WTABL);
    __half* WTBAH = (__half*)(F + OFF_WTBAH);
    __half* WTBAL = (__half*)(F + OFF_WTBAL);

    int* RP2 = I + IOFF_RP2;
    int* CNT2 = I + IOFF_CNT2;
    int* FILL2 = I + IOFF_FILL2;
    int* SRT = I + IOFF_SRT;
    int* BSUM = I + IOFF_BSUM;

    const int FinL[3] = {128, 256, 256};
    const int FoutL[3] = {256, 256, 16};

    // ---- all dv projections upfront: SV + l*512 {+0: ab, +256: ba} ----
    for (int l = 0; l < 3; l++)
        wv2_kernel<<<dim3(cdiv(FinL[l], 8), 2), 256>>>(
            Wab[l], adab[l], SV + l * 512, Wba[l], adba[l], SV + l * 512 + 256,
            FinL[l], FoutL[l]);

    // ---- concatenated CSR build ----
    const int NSEG = NA + NB;
    const int nScanBlk = cdiv(NSEG, 1024);
    cudaMemsetAsync(CNT2, 0, NSEG * sizeof(int), 0);
    hist2_kernel<<<cdiv(2 * NEDGE, 256), 256>>>(ei_ab, ei_ba, CNT2);
    scan1_kernel<<<nScanBlk, 1024>>>(CNT2, RP2, BSUM, NSEG);
    scan2_kernel<<<1, 128>>>(BSUM, nScanBlk);
    scan3_kernel<<<nScanBlk, 1024>>>(RP2, BSUM, NSEG);
    cudaMemsetAsync(FILL2, 0, NSEG * sizeof(int), 0);
    scatter2_kernel<<<cdiv(2 * NEDGE, 256), 256>>>(ei_ab, ei_ba, RP2, FILL2, SRT);

    // ---- layer-1 X split + dd ----
    splitX_kernel<<<cdiv(NA, 8), 256>>>(xAin, XAH, XAL, SV + 256, DDBA, NA);
    splitX_kernel<<<cdiv(NB, 8), 256>>>(xBin, XBH, XBL, SV + 0, DDAB, NB);

    for (int l = 0; l < 3; l++) {
        int Fin = FinL[l];

        if (l < 2) {
            cudaMemsetAsync(SSAB, 0, 2 * NA * sizeof(float), 0);  // SSAB + SSBA
            transpose2split_kernel<<<dim3(256 / 32, Fin / 32, 2), dim3(32, 8)>>>(
                Wab[l], WTABH, WTABL, Wba[l], WTBAH, WTBAL, Fin, 256);
            gemm2_kernel<<<dim3(cdiv(NA, 128), 2, 2), 256>>>(
                XAH, XAL, WTABH, WTABL, HABh, asab[l], SSAB,
                XBH, XBL, WTBAH, WTBAL, HBAh, asba[l], SSBA, NA, Fin);

            gat256h2_kernel<<<cdiv(NA + NB, 8), 256>>>(
                RP2, SRT,
                SSAB, DDAB, HABh, bab[l], XBH, XBL, SV + (l + 1) * 512, DDAB,
                SSBA, DDBA, HBAh, bba[l], XAH, XAL, SV + (l + 1) * 512 + 256, DDBA);
        } else {
            gemm_n16_2_kernel<<<dim3(cdiv(NA, 32), 2), 512>>>(
                XAH, XAL, Wab[l], HABf, asab[l], SSAB,
                XBH, XBL, Wba[l], HBAf, asba[l], SSBA, NA);

            gat16_2_kernel<<<cdiv(NA + NB, 8), 256>>>(
                RP2, SRT,
                SSAB, DDAB, HABf, bab[l], xbOut,
                SSBA, DDBA, HBAf, bba[l], xaOut);
        }
    }

    // ---- readout ----
    cudaMemsetAsync(SUM16, 0, 16 * sizeof(float), 0);
    sumrows16_kernel<<<256, 256>>>(xbOut, dstI, SUM16, LPRED);
    pred_kernel<<<cdiv(LPRED, 256), 256>>>(xaOut, srcI, SUM16, pred, LPRED);
}

// round 11
// speedup vs baseline: 1.0505x; 1.0505x over previous
#include <cuda_runtime.h>
#include <cuda_fp16.h>
#include <math.h>
#include <stdint.h>

#define NA 50000
#define NB 50000
#define NEDGE 1000000
#define LPRED 100000

// ---------------- device scratch pools ----------------
#define OFF_XAH   0u
#define OFF_XAL   6400000u
#define OFF_XBH   12800000u
#define OFF_XBL   19200000u
#define OFF_HAB   25600000u
#define OFF_HBA   38400000u
#define OFF_SSAB  51200000u
#define OFF_SSBA  51250000u
#define OFF_DDAB  51300000u
#define OFF_DDBA  51350000u
#define OFF_SV    51400000u             // 6*256 dv vectors (padded 2048)
#define OFF_SUM16 51402048u
#define OFF_WTABH 51402064u
#define OFF_WTABL 51434832u
#define OFF_WTBAH 51467600u
#define OFF_WTBAL 51500368u
#define FPOOL_N   51533136u

#define IOFF_RP2   0u
#define IOFF_CNT2  100001u
#define IOFF_FILL2 200001u
#define IOFF_SRT   300001u
#define IOFF_BSUM  2300001u
#define IPOOL_N    2300129u

static __device__ float g_fpool[FPOOL_N];
static __device__ int   g_ipool[IPOOL_N];

// ---------------- fp16 hi/lo split helpers ----------------
__device__ __forceinline__ void split2(float x, float y, __half2* ph, __half2* pl) {
    float hx = __uint_as_float(__float_as_uint(x) & 0xFFFFE000u);
    float hy = __uint_as_float(__float_as_uint(y) & 0xFFFFE000u);
    *ph = __halves2half2(__float2half_rn(hx), __float2half_rn(hy));
    *pl = __halves2half2(__float2half_rn(x - hx), __float2half_rn(y - hy));
}

__device__ __forceinline__ void split_store4(float4 v, __half* ph, __half* pl) {
    __half2 h01, l01, h23, l23;
    split2(v.x, v.y, &h01, &l01);
    split2(v.z, v.w, &h23, &l23);
    *(__half2*)(ph)     = h01;
    *(__half2*)(ph + 2) = h23;
    *(__half2*)(pl)     = l01;
    *(__half2*)(pl + 2) = l23;
}

#define MMA_F16(cc, aa, bb)                                                         \
    asm volatile(                                                                   \
        "mma.sync.aligned.m16n8k16.row.col.f32.f16.f16.f32 "                        \
        "{%0,%1,%2,%3},{%4,%5,%6,%7},{%8,%9},{%0,%1,%2,%3};\n"                      \
        : "+f"((cc)[0]), "+f"((cc)[1]), "+f"((cc)[2]), "+f"((cc)[3])                \
        : "r"((aa)[0]), "r"((aa)[1]), "r"((aa)[2]), "r"((aa)[3]),                   \
          "r"((bb)[0]), "r"((bb)[1]))

// ---------------- merged-z HMMA GEMM (R7 staging: direct LDG.128 + STS) ----------------
// blockIdx.z selects direction (streaming access -> L2-safe to merge).
// C(half)[M,256] = A[M,K] @ Bt[256,K]^T, fp16 hi/lo 3-term;
// fused ssOut[r] += sum_c C[r,c]*sv[c].
__global__ void __launch_bounds__(256) gemm2_kernel(
    const __half* __restrict__ A0h, const __half* __restrict__ A0l,
    const __half* __restrict__ B0h, const __half* __restrict__ B0l,
    __half* __restrict__ C0, const float* __restrict__ sv0, float* __restrict__ ss0,
    const __half* __restrict__ A1h, const __half* __restrict__ A1l,
    const __half* __restrict__ B1h, const __half* __restrict__ B1l,
    __half* __restrict__ C1, const float* __restrict__ sv1, float* __restrict__ ss1,
    int M, int K) {
    __shared__ __half Ah[128][40], Al[128][40], Bh[128][40], Bl[128][40];
    __shared__ float ssred[128];

    const __half* Ahg = blockIdx.z ? A1h : A0h;
    const __half* Alg = blockIdx.z ? A1l : A0l;
    const __half* Bhg = blockIdx.z ? B1h : B0h;
    const __half* Blg = blockIdx.z ? B1l : B0l;
    __half* C = blockIdx.z ? C1 : C0;
    const float* sv = blockIdx.z ? sv1 : sv0;
    float* ssOut = blockIdx.z ? ss1 : ss0;

    int tid = threadIdx.x;
    int warp = tid >> 5, lane = tid & 31;
    int g = lane >> 2, tg = lane & 3;
    int wm = warp >> 2, wn = warp & 3;
    int bm = blockIdx.x * 128, bn = blockIdx.y * 128;

    float c[4][4][4] = {};

    for (int k0 = 0; k0 < K; k0 += 32) {
        // stage (pure copy): 512 uint4 per array, 2 per thread per array
#pragma unroll
        for (int j = 0; j < 2; j++) {
            int idx = tid + j * 256;
            int row = idx >> 2, q = (idx & 3) * 8;
            uint4 vh = make_uint4(0, 0, 0, 0), vl = make_uint4(0, 0, 0, 0);
            int gr = bm + row;
            if (gr < M) {
                vh = *(const uint4*)(Ahg + (size_t)gr * K + k0 + q);
                vl = *(const uint4*)(Alg + (size_t)gr * K + k0 + q);
            }
            *(uint4*)&Ah[row][q] = vh;
            *(uint4*)&Al[row][q] = vl;
            uint4 wh = *(const uint4*)(Bhg + (size_t)(bn + row) * K + k0 + q);
            uint4 wl = *(const uint4*)(Blg + (size_t)(bn + row) * K + k0 + q);
            *(uint4*)&Bh[row][q] = wh;
            *(uint4*)&Bl[row][q] = wl;
        }
        __syncthreads();

#pragma unroll
        for (int ks = 0; ks < 2; ks++) {
            int kc = ks * 16 + tg * 2;
            unsigned ah[4][4], al[4][4], bh[4][2], bl[4][2];
#pragma unroll
            for (int mt = 0; mt < 4; mt++) {
                int r = wm * 64 + mt * 16 + g;
                ah[mt][0] = *(const unsigned*)&Ah[r][kc];
                ah[mt][1] = *(const unsigned*)&Ah[r + 8][kc];
                ah[mt][2] = *(const unsigned*)&Ah[r][kc + 8];
                ah[mt][3] = *(const unsigned*)&Ah[r + 8][kc + 8];
                al[mt][0] = *(const unsigned*)&Al[r][kc];
                al[mt][1] = *(const unsigned*)&Al[r + 8][kc];
                al[mt][2] = *(const unsigned*)&Al[r][kc + 8];
                al[mt][3] = *(const unsigned*)&Al[r + 8][kc + 8];
            }
#pragma unroll
            for (int nt = 0; nt < 4; nt++) {
                int n = wn * 32 + nt * 8 + g;
                bh[nt][0] = *(const unsigned*)&Bh[n][kc];
                bh[nt][1] = *(const unsigned*)&Bh[n][kc + 8];
                bl[nt][0] = *(const unsigned*)&Bl[n][kc];
                bl[nt][1] = *(const unsigned*)&Bl[n][kc + 8];
            }
#pragma unroll
            for (int mt = 0; mt < 4; mt++)
#pragma unroll
                for (int nt = 0; nt < 4; nt++) {
                    MMA_F16(c[mt][nt], ah[mt], bl[nt]);
                    MMA_F16(c[mt][nt], al[mt], bh[nt]);
                    MMA_F16(c[mt][nt], ah[mt], bh[nt]);
                }
        }
        __syncthreads();
    }

    // ss: per-row dot of C with sv
    if (tid < 128) ssred[tid] = 0.f;
    __syncthreads();
#pragma unroll
    for (int mt = 0; mt < 4; mt++) {
        float p0 = 0.f, p1 = 0.f;
#pragma unroll
        for (int nt = 0; nt < 4; nt++) {
            int col0 = bn + wn * 32 + nt * 8 + tg * 2;
            float2 sva = __ldg((const float2*)sv + (col0 >> 1));
            p0 += c[mt][nt][0] * sva.x + c[mt][nt][1] * sva.y;
            p1 += c[mt][nt][2] * sva.x + c[mt][nt][3] * sva.y;
        }
        p0 += __shfl_xor_sync(0xffffffffu, p0, 1);
        p0 += __shfl_xor_sync(0xffffffffu, p0, 2);
        p1 += __shfl_xor_sync(0xffffffffu, p1, 1);
        p1 += __shfl_xor_sync(0xffffffffu, p1, 2);
        if (tg == 0) {
            int rl = wm * 64 + mt * 16 + g;
            atomicAdd(&ssred[rl], p0);
            atomicAdd(&ssred[rl + 8], p1);
        }
    }
    __syncthreads();
    if (tid < 128) {
        int row = bm + tid;
        if (row < M) atomicAdd(ssOut + row, ssred[tid]);
    }

    // C store (fp16)
#pragma unroll
    for (int mt = 0; mt < 4; mt++) {
        int r0 = bm + wm * 64 + mt * 16 + g;
#pragma unroll
        for (int nt = 0; nt < 4; nt++) {
            int cc = bn + wn * 32 + nt * 8 + tg * 2;
            __half2 p0 = __floats2half2_rn(c[mt][nt][0], c[mt][nt][1]);
            __half2 p1 = __floats2half2_rn(c[mt][nt][2], c[mt][nt][3]);
            if (r0 < M)     *(__half2*)(C + (size_t)r0 * 256 + cc) = p0;
            if (r0 + 8 < M) *(__half2*)(C + (size_t)(r0 + 8) * 256 + cc) = p1;
        }
    }
}

// ---------------- transpose + split weights ----------------
__global__ void transpose2split_kernel(const float* __restrict__ W0,
                                       __half* __restrict__ T0h, __half* __restrict__ T0l,
                                       const float* __restrict__ W1,
                                       __half* __restrict__ T1h, __half* __restrict__ T1l,
                                       int K, int N) {
    __shared__ float t[32][33];
    const float* W = blockIdx.z ? W1 : W0;
    __half* Th = blockIdx.z ? T1h : T0h;
    __half* Tl = blockIdx.z ? T1l : T0l;
    int n0 = blockIdx.x * 32, k0 = blockIdx.y * 32;
#pragma unroll
    for (int i = 0; i < 4; i++) {
        int k = k0 + threadIdx.y + i * 8;
        t[threadIdx.y + i * 8][threadIdx.x] = W[(size_t)k * N + n0 + threadIdx.x];
    }
    __syncthreads();
#pragma unroll
    for (int i = 0; i < 4; i++) {
        int n = n0 + threadIdx.y + i * 8;
        float v = t[threadIdx.x][threadIdx.y + i * 8];
        float hv = __uint_as_float(__float_as_uint(v) & 0xFFFFE000u);
        Th[(size_t)n * K + k0 + threadIdx.x] = __float2half_rn(hv);
        Tl[(size_t)n * K + k0 + threadIdx.x] = __float2half_rn(v - hv);
    }
}

// ---------------- layer-1 X split (K=128) + dd dot ----------------
__global__ void splitX_kernel(const float* __restrict__ X,
                              __half* __restrict__ Xh, __half* __restrict__ Xl,
                              const float* __restrict__ dv, float* __restrict__ dd,
                              int M) {
    int w = (blockIdx.x * blockDim.x + threadIdx.x) >> 5;
    int lane = threadIdx.x & 31;
    if (w >= M) return;
    float4 v = *(const float4*)(X + (size_t)w * 128 + lane * 4);
    float4 dvv = __ldg((const float4*)dv + lane);
    float acc = v.x * dvv.x + v.y * dvv.y + v.z * dvv.z + v.w * dvv.w;
    split_store4(v, Xh + (size_t)w * 128 + lane * 4, Xl + (size_t)w * 128 + lane * 4);
#pragma unroll
    for (int o = 16; o; o >>= 1) acc += __shfl_xor_sync(0xffffffffu, acc, o);
    if (lane == 0) dd[w] = acc;
}

// ---------------- small-N GEMM (layer 3): X from hi+lo halves, fused ss ----------------
__global__ void __launch_bounds__(512) gemm_n16_kernel(const __half* __restrict__ Xh,
                                                       const __half* __restrict__ Xl,
                                                       const float* __restrict__ W,
                                                       float* __restrict__ H, int M,
                                                       const float* __restrict__ sv,
                                                       float* __restrict__ ssOut) {
    __shared__ float Ws[256 * 16];
    __shared__ float Xs[32 * 256];
    int tid = threadIdx.x;
    int row0 = blockIdx.x * 32;
    for (int i = tid; i < 256 * 16 / 4; i += 512)
        *(float4*)&Ws[i * 4] = *(const float4*)(W + i * 4);
#pragma unroll
    for (int i = 0; i < 4; i++) {
        int lin = tid + i * 512;
        int r = lin / 64;
        int c4 = lin % 64;
        float4 v = make_float4(0.f, 0.f, 0.f, 0.f);
        if (row0 + r < M) {
            uint2 vh = *(const uint2*)(Xh + (size_t)(row0 + r) * 256 + c4 * 4);
            uint2 vl = *(const uint2*)(Xl + (size_t)(row0 + r) * 256 + c4 * 4);
            const __half2* ph = (const __half2*)&vh;
            const __half2* pl = (const __half2*)&vl;
            float2 a0 = __half22float2(ph[0]), a1 = __half22float2(ph[1]);
            float2 b0 = __half22float2(pl[0]), b1 = __half22float2(pl[1]);
            v = make_float4(a0.x + b0.x, a0.y + b0.y, a1.x + b1.x, a1.y + b1.y);
        }
        *(float4*)&Xs[r * 256 + c4 * 4] = v;
    }
    __syncthreads();

    int r = tid / 16, c = tid % 16;
    float acc = 0.f;
#pragma unroll 8
    for (int k = 0; k < 256; k++) acc += Xs[r * 256 + k] * Ws[k * 16 + c];

    float sp = acc * __ldg(sv + c);
    sp += __shfl_xor_sync(0xffffffffu, sp, 1);
    sp += __shfl_xor_sync(0xffffffffu, sp, 2);
    sp += __shfl_xor_sync(0xffffffffu, sp, 4);
    sp += __shfl_xor_sync(0xffffffffu, sp, 8);
    if (row0 + r < M) {
        if ((tid & 15) == 0) ssOut[row0 + r] = sp;
        H[(size_t)(row0 + r) * 16 + c] = acc;
    }
}

// ---------------- fused dual W@a ----------------
__global__ void wv2_kernel(const float* __restrict__ W0, const float* __restrict__ a0,
                           float* __restrict__ o0,
                           const float* __restrict__ W1, const float* __restrict__ a1,
                           float* __restrict__ o1, int Fin, int Fout) {
    const float* W = blockIdx.y ? W1 : W0;
    const float* a = blockIdx.y ? a1 : a0;
    float* o = blockIdx.y ? o1 : o0;
    int w = (blockIdx.x * blockDim.x + threadIdx.x) >> 5;
    int lane = threadIdx.x & 31;
    if (w >= Fin) return;
    float s = 0.f;
    for (int j = lane; j < Fout; j += 32) s += W[(size_t)w * Fout + j] * a[j];
    for (int o2 = 16; o2; o2 >>= 1) s += __shfl_down_sync(0xffffffffu, s, o2);
    if (lane == 0) o[w] = s;
}

// ---------------- concatenated 2-direction CSR build ----------------
__global__ void hist2_kernel(const int* __restrict__ eab, const int* __restrict__ eba,
                             int* __restrict__ cnt) {
    int e = blockIdx.x * blockDim.x + threadIdx.x;
    if (e < NEDGE) atomicAdd(&cnt[eab[NEDGE + e]], 1);
    else if (e < 2 * NEDGE) atomicAdd(&cnt[NB + eba[NEDGE + e - NEDGE]], 1);
}

__global__ void scan1_kernel(const int* __restrict__ cnt, int* __restrict__ rowptr,
                             int* __restrict__ bsum, int n) {
    __shared__ int sh[1024];
    int i = blockIdx.x * 1024 + threadIdx.x;
    int v = (i < n) ? cnt[i] : 0;
    sh[threadIdx.x] = v;
    __syncthreads();
    for (int off = 1; off < 1024; off <<= 1) {
        int t = (threadIdx.x >= off) ? sh[threadIdx.x - off] : 0;
        __syncthreads();
        sh[threadIdx.x] += t;
        __syncthreads();
    }
    if (i < n) rowptr[i + 1] = sh[threadIdx.x];
    if (threadIdx.x == 1023) bsum[blockIdx.x] = sh[1023];
}

__global__ void scan2_kernel(int* __restrict__ bsum, int nb) {
    __shared__ int sh[128];
    int t = threadIdx.x;
    int v = (t < nb) ? bsum[t] : 0;
    sh[t] = v;
    __syncthreads();
    for (int off = 1; off < 128; off <<= 1) {
        int u = (t >= off) ? sh[t - off] : 0;
        __syncthreads();
        sh[t] += u;
        __syncthreads();
    }
    if (t < nb) bsum[t] = sh[t] - v;
}

__global__ void scan3_kernel(int* __restrict__ rowptr, const int* __restrict__ bsum, int n) {
    int i = blockIdx.x * 1024 + threadIdx.x;
    if (i < n) rowptr[i + 1] += bsum[blockIdx.x];
    if (i == 0) rowptr[0] = 0;
}

__global__ void scatter2_kernel(const int* __restrict__ eab, const int* __restrict__ eba,
                                const int* __restrict__ rowptr, int* __restrict__ fill,
                                int* __restrict__ sorted) {
    int e = blockIdx.x * blockDim.x + threadIdx.x;
    int s, seg;
    if (e < NEDGE) { s = eab[e]; seg = eab[NEDGE + e]; }
    else if (e < 2 * NEDGE) { int e2 = e - NEDGE; s = eba[e2]; seg = NB + eba[NEDGE + e2]; }
    else return;
    int p = rowptr[seg] + atomicAdd(&fill[seg], 1);
    sorted[p] = s;
}

// ---------------- fused GAT (FOUT=256): fp16 gather; writes split X + next dd ----------------
__global__ void __launch_bounds__(256) gat256h_kernel(const int* __restrict__ rowptr,
                                                      const int* __restrict__ ssrc,
                                                      const float* __restrict__ ss,
                                                      const float* __restrict__ dd,
                                                      const __half* __restrict__ H,
                                                      const float* __restrict__ bias,
                                                      __half* __restrict__ Xh,
                                                      __half* __restrict__ Xl,
                                                      const float* __restrict__ dvn,
                                                      float* __restrict__ ddn,
                                                      int ndst) {
    int w = (blockIdx.x * blockDim.x + threadIdx.x) >> 5;
    int lane = threadIdx.x & 31;
    if (w >= ndst) return;
    int b0 = rowptr[w], b1 = rowptr[w + 1];
    float ddv = dd[w];

    float mx = __int_as_float(0xff800000);
    for (int i = b0 + lane; i < b1; i += 32) {
        float v = __ldg(ss + ssrc[i]) + ddv;
        v = v > 0.f ? v : 0.2f * v;
        mx = fmaxf(mx, v);
    }
#pragma unroll
    for (int o = 16; o; o >>= 1) mx = fmaxf(mx, __shfl_xor_sync(0xffffffffu, mx, o));

    float acc[8] = {};
    float sum = 0.f;
    for (int base = b0; base < b1; base += 32) {
        int i = base + lane;
        float wgt = 0.f;
        int s = 0;
        if (i < b1) {
            s = ssrc[i];
            float v = __ldg(ss + s) + ddv;
            v = v > 0.f ? v : 0.2f * v;
            wgt = __expf(v - mx);
        }
        sum += wgt;
        int nn = min(32, b1 - base);
        for (int t = 0; t < nn; t++) {
            float wt = __shfl_sync(0xffffffffu, wgt, t);
            int st = __shfl_sync(0xffffffffu, s, t);
            uint4 u = __ldg((const uint4*)(H + (size_t)st * 256) + lane);
            const __half2* hh = (const __half2*)&u;
#pragma unroll
            for (int j = 0; j < 4; j++) {
                float2 f = __half22float2(hh[j]);
                acc[2 * j]     += wt * f.x;
                acc[2 * j + 1] += wt * f.y;
            }
        }
    }
#pragma unroll
    for (int o = 16; o; o >>= 1) sum += __shfl_xor_sync(0xffffffffu, sum, o);
    float inv = 1.f / (sum + 1e-16f);

    float4 bb0 = __ldg((const float4*)bias + lane * 2);
    float4 bb1 = __ldg((const float4*)bias + lane * 2 + 1);
    float4 o0, o1;
    o0.x = fmaxf(acc[0] * inv + bb0.x, 0.f); o0.y = fmaxf(acc[1] * inv + bb0.y, 0.f);
    o0.z = fmaxf(acc[2] * inv + bb0.z, 0.f); o0.w = fmaxf(acc[3] * inv + bb0.w, 0.f);
    o1.x = fmaxf(acc[4] * inv + bb1.x, 0.f); o1.y = fmaxf(acc[5] * inv + bb1.y, 0.f);
    o1.z = fmaxf(acc[6] * inv + bb1.z, 0.f); o1.w = fmaxf(acc[7] * inv + bb1.w, 0.f);

    union U4 { __half2 h2[4]; uint4 u; };
    U4 uh, ul;
    split2(o0.x, o0.y, &uh.h2[0], &ul.h2[0]);
    split2(o0.z, o0.w, &uh.h2[1], &ul.h2[1]);
    split2(o1.x, o1.y, &uh.h2[2], &ul.h2[2]);
    split2(o1.z, o1.w, &uh.h2[3], &ul.h2[3]);
    *(uint4*)(Xh + (size_t)w * 256 + lane * 8) = uh.u;
    *(uint4*)(Xl + (size_t)w * 256 + lane * 8) = ul.u;

    float4 dva = __ldg((const float4*)dvn + lane * 2);
    float4 dvb = __ldg((const float4*)dvn + lane * 2 + 1);
    float dq = o0.x * dva.x + o0.y * dva.y + o0.z * dva.z + o0.w * dva.w
             + o1.x * dvb.x + o1.y * dvb.y + o1.z * dvb.z + o1.w * dvb.w;
#pragma unroll
    for (int o = 16; o; o >>= 1) dq += __shfl_xor_sync(0xffffffffu, dq, o);
    if (lane == 0) ddn[w] = dq;
}

// ---------------- fused GAT (FOUT=16, final layer, fp32 H) ----------------
__global__ void __launch_bounds__(256) gat16_kernel(const int* __restrict__ rowptr,
                                                    const int* __restrict__ ssrc,
                                                    const float* __restrict__ ss,
                                                    const float* __restrict__ dd,
                                                    const float* __restrict__ H,
                                                    const float* __restrict__ bias,
                                                    float* __restrict__ out, int ndst) {
    int w = (blockIdx.x * blockDim.x + threadIdx.x) >> 5;
    int lane = threadIdx.x & 31;
    if (w >= ndst) return;
    int b0 = rowptr[w], b1 = rowptr[w + 1];
    float ddv = dd[w];
    int half = lane >> 4, fl = lane & 15;

    float mx = __int_as_float(0xff800000);
    for (int i = b0 + lane; i < b1; i += 32) {
        float v = __ldg(ss + ssrc[i]) + ddv;
        v = v > 0.f ? v : 0.2f * v;
        mx = fmaxf(mx, v);
    }
#pragma unroll
    for (int o = 16; o; o >>= 1) mx = fmaxf(mx, __shfl_xor_sync(0xffffffffu, mx, o));

    float acc = 0.f;
    float sum = 0.f;
    for (int base = b0; base < b1; base += 32) {
        int i = base + lane;
        float wgt = 0.f;
        int s = 0;
        if (i < b1) {
            s = ssrc[i];
            float v = __ldg(ss + s) + ddv;
            v = v > 0.f ? v : 0.2f * v;
            wgt = __expf(v - mx);
        }
        sum += wgt;
        int nn = min(32, b1 - base);
        for (int t = 0; t < nn; t += 2) {
            int tt = t + half;
            float wt = __shfl_sync(0xffffffffu, wgt, tt);
            int st = __shfl_sync(0xffffffffu, s, tt);
            if (tt < nn) acc += wt * __ldg(H + (size_t)st * 16 + fl);
        }
    }
#pragma unroll
    for (int o = 16; o; o >>= 1) sum += __shfl_xor_sync(0xffffffffu, sum, o);
    acc += __shfl_xor_sync(0xffffffffu, acc, 16);
    float inv = 1.f / (sum + 1e-16f);
    if (lane < 16)
        out[(size_t)w * 16 + lane] = acc * inv + __ldg(bias + lane);
}

// ---------------- readout ----------------
__global__ void sumrows16_kernel(const float* __restrict__ xb, const int* __restrict__ dstidx,
                                 float* __restrict__ out16, int L) {
    __shared__ float sh[16];
    if (threadIdx.x < 16) sh[threadIdx.x] = 0.f;
    __syncthreads();
    float loc[16];
#pragma unroll
    for (int k = 0; k < 16; k++) loc[k] = 0.f;
    for (int t = blockIdx.x * blockDim.x + threadIdx.x; t < L; t += gridDim.x * blockDim.x) {
        const float* row = xb + (size_t)dstidx[t] * 16;
#pragma unroll
        for (int k = 0; k < 16; k++) loc[k] += row[k];
    }
#pragma unroll
    for (int k = 0; k < 16; k++) atomicAdd(&sh[k], loc[k]);
    __syncthreads();
    if (threadIdx.x < 16) atomicAdd(&out16[threadIdx.x], sh[threadIdx.x]);
}

__global__ void pred_kernel(const float* __restrict__ xa, const int* __restrict__ srcidx,
                            const float* __restrict__ sum16, float* __restrict__ pred, int L) {
    int t = blockIdx.x * blockDim.x + threadIdx.x;
    if (t >= L) return;
    const float* row = xa + (size_t)srcidx[t] * 16;
    float s = 0.f;
#pragma unroll
    for (int k = 0; k < 16; k++) s += row[k] * __ldg(sum16 + k);
    pred[t] = s;
}

// ---------------- host orchestration ----------------
static inline int cdiv(int a, int b) { return (a + b - 1) / b; }

extern "C" void kernel_launch(void* const* d_in, const int* in_sizes, int n_in,
                              void* d_out, int out_size) {
    const float* xAin = (const float*)d_in[0];
    const float* xBin = (const float*)d_in[1];
    const int* ei_ab = (const int*)d_in[2];
    const int* ei_ba = (const int*)d_in[3];
    const int* srcI = (const int*)d_in[4];
    const int* dstI = (const int*)d_in[5];

    const float* Wab[3]  = {(const float*)d_in[6],  (const float*)d_in[14], (const float*)d_in[22]};
    const float* asab[3] = {(const float*)d_in[7],  (const float*)d_in[15], (const float*)d_in[23]};
    const float* adab[3] = {(const float*)d_in[8],  (const float*)d_in[16], (const float*)d_in[24]};
    const float* bab[3]  = {(const float*)d_in[9],  (const float*)d_in[17], (const float*)d_in[25]};
    const float* Wba[3]  = {(const float*)d_in[10], (const float*)d_in[18], (const float*)d_in[26]};
    const float* asba[3] = {(const float*)d_in[11], (const float*)d_in[19], (const float*)d_in[27]};
    const float* adba[3] = {(const float*)d_in[12], (const float*)d_in[20], (const float*)d_in[28]};
    const float* bba[3]  = {(const float*)d_in[13], (const float*)d_in[21], (const float*)d_in[29]};

    float* out = (float*)d_out;
    float* pred = out;
    float* xaOut = out + LPRED;
    float* xbOut = xaOut + (size_t)NA * 16;

    float* F = nullptr;
    int* I = nullptr;
    cudaGetSymbolAddress((void**)&F, g_fpool);
    cudaGetSymbolAddress((void**)&I, g_ipool);

    __half* XAH = (__half*)(F + OFF_XAH);
    __half* XAL = (__half*)(F + OFF_XAL);
    __half* XBH = (__half*)(F + OFF_XBH);
    __half* XBL = (__half*)(F + OFF_XBL);
    float* HABf = F + OFF_HAB;
    float* HBAf = F + OFF_HBA;
    __half* HABh = (__half*)(F + OFF_HAB);
    __half* HBAh = (__half*)(F + OFF_HBA);
    float* SSAB = F + OFF_SSAB;
    float* SSBA = F + OFF_SSBA;
    float* DDAB = F + OFF_DDAB;
    float* DDBA = F + OFF_DDBA;
    float* SV = F + OFF_SV;
    float* SUM16 = F + OFF_SUM16;
    __half* WTABH = (__half*)(F + OFF_WTABH);
    __half* WTABL = (__half*)(F + OFF_WTABL);
    __half* WTBAH = (__half*)(F + OFF_WTBAH);
    __half* WTBAL = (__half*)(F + OFF_WTBAL);

    int* RP2 = I + IOFF_RP2;
    int* CNT2 = I + IOFF_CNT2;
    int* FILL2 = I + IOFF_FILL2;
    int* SRT = I + IOFF_SRT;
    int* BSUM = I + IOFF_BSUM;

    const int FinL[3] = {128, 256, 256};
    const int FoutL[3] = {256, 256, 16};

    // ---- all dv projections upfront: SV + l*512 {+0: ab, +256: ba} ----
    for (int l = 0; l < 3; l++)
        wv2_kernel<<<dim3(cdiv(FinL[l], 8), 2), 256>>>(
            Wab[l], adab[l], SV + l * 512, Wba[l], adba[l], SV + l * 512 + 256,
            FinL[l], FoutL[l]);

    // ---- concatenated CSR build ----
    const int NSEG = NA + NB;
    const int nScanBlk = cdiv(NSEG, 1024);
    cudaMemsetAsync(CNT2, 0, NSEG * sizeof(int), 0);
    hist2_kernel<<<cdiv(2 * NEDGE, 256), 256>>>(ei_ab, ei_ba, CNT2);
    scan1_kernel<<<nScanBlk, 1024>>>(CNT2, RP2, BSUM, NSEG);
    scan2_kernel<<<1, 128>>>(BSUM, nScanBlk);
    scan3_kernel<<<nScanBlk, 1024>>>(RP2, BSUM, NSEG);
    cudaMemsetAsync(FILL2, 0, NSEG * sizeof(int), 0);
    scatter2_kernel<<<cdiv(2 * NEDGE, 256), 256>>>(ei_ab, ei_ba, RP2, FILL2, SRT);

    // ---- layer-1 X split + dd ----
    splitX_kernel<<<cdiv(NA, 8), 256>>>(xAin, XAH, XAL, SV + 256, DDBA, NA);
    splitX_kernel<<<cdiv(NB, 8), 256>>>(xBin, XBH, XBL, SV + 0, DDAB, NB);

    for (int l = 0; l < 3; l++) {
        int Fin = FinL[l];

        if (l < 2) {
            cudaMemsetAsync(SSAB, 0, 2 * NA * sizeof(float), 0);  // SSAB + SSBA
            transpose2split_kernel<<<dim3(256 / 32, Fin / 32, 2), dim3(32, 8)>>>(
                Wab[l], WTABH, WTABL, Wba[l], WTBAH, WTBAL, Fin, 256);
            // single merged-z GEMM launch (streaming -> L2-safe merge)
            gemm2_kernel<<<dim3(cdiv(NA, 128), 2, 2), 256>>>(
                XAH, XAL, WTABH, WTABL, HABh, asab[l], SSAB,
                XBH, XBL, WTBAH, WTBAL, HBAh, asba[l], SSBA, NA, Fin);

            // UNMERGED gat launches (reuse-dependent gather -> keep working set small)
            gat256h_kernel<<<cdiv(NB, 8), 256>>>(RP2, SRT, SSAB, DDAB, HABh, bab[l],
                                                 XBH, XBL, SV + (l + 1) * 512, DDAB, NB);
            gat256h_kernel<<<cdiv(NA, 8), 256>>>(RP2 + NB, SRT, SSBA, DDBA, HBAh, bba[l],
                                                 XAH, XAL, SV + (l + 1) * 512 + 256, DDBA, NA);
        } else {
            gemm_n16_kernel<<<cdiv(NA, 32), 512>>>(XAH, XAL, Wab[l], HABf, NA, asab[l], SSAB);
            gemm_n16_kernel<<<cdiv(NB, 32), 512>>>(XBH, XBL, Wba[l], HBAf, NB, asba[l], SSBA);

            gat16_kernel<<<cdiv(NB, 8), 256>>>(RP2, SRT, SSAB, DDAB, HABf, bab[l], xbOut, NB);
            gat16_kernel<<<cdiv(NA, 8), 256>>>(RP2 + NB, SRT, SSBA, DDBA, HBAf, bba[l], xaOut, NA);
        }
    }

    // ---- readout ----
    cudaMemsetAsync(SUM16, 0, 16 * sizeof(float), 0);
    sumrows16_kernel<<<256, 256>>>(xbOut, dstI, SUM16, LPRED);
    pred_kernel<<<cdiv(LPRED, 256), 256>>>(xaOut, srcI, SUM16, pred, LPRED);
}

// round 12
// speedup vs baseline: 1.1460x; 1.0909x over previous
#include <cuda_runtime.h>
#include <cuda_fp16.h>
#include <math.h>
#include <stdint.h>

#define NA 50000
#define NB 50000
#define NEDGE 1000000
#define LPRED 100000

// ---------------- device scratch pools ----------------
#define OFF_XAH   0u
#define OFF_XAL   6400000u
#define OFF_XBH   12800000u
#define OFF_XBL   19200000u
#define OFF_HAB   25600000u
#define OFF_HBA   38400000u
#define OFF_SSAB  51200000u
#define OFF_SSBA  51250000u
#define OFF_DDAB  51300000u
#define OFF_DDBA  51350000u
#define OFF_SV    51400000u             // 6*256 dv vectors (padded 2048)
#define OFF_SUM16 51402048u
#define OFF_WTABH 51402064u
#define OFF_WTABL 51434832u
#define OFF_WTBAH 51467600u
#define OFF_WTBAL 51500368u
#define FPOOL_N   51533136u

#define IOFF_RP2   0u
#define IOFF_CNT2  100001u
#define IOFF_FILL2 200001u
#define IOFF_SRT   300001u
#define IOFF_BSUM  2300001u
#define IPOOL_N    2300129u

static __device__ float g_fpool[FPOOL_N];
static __device__ int   g_ipool[IPOOL_N];

// ---------------- fp16 hi/lo split helpers ----------------
__device__ __forceinline__ void split2(float x, float y, __half2* ph, __half2* pl) {
    float hx = __uint_as_float(__float_as_uint(x) & 0xFFFFE000u);
    float hy = __uint_as_float(__float_as_uint(y) & 0xFFFFE000u);
    *ph = __halves2half2(__float2half_rn(hx), __float2half_rn(hy));
    *pl = __halves2half2(__float2half_rn(x - hx), __float2half_rn(y - hy));
}

__device__ __forceinline__ void split_store4(float4 v, __half* ph, __half* pl) {
    __half2 h01, l01, h23, l23;
    split2(v.x, v.y, &h01, &l01);
    split2(v.z, v.w, &h23, &l23);
    *(__half2*)(ph)     = h01;
    *(__half2*)(ph + 2) = h23;
    *(__half2*)(pl)     = l01;
    *(__half2*)(pl + 2) = l23;
}

#define MMA_F16(cc, aa, bb)                                                         \
    asm volatile(                                                                   \
        "mma.sync.aligned.m16n8k16.row.col.f32.f16.f16.f32 "                        \
        "{%0,%1,%2,%3},{%4,%5,%6,%7},{%8,%9},{%0,%1,%2,%3};\n"                      \
        : "+f"((cc)[0]), "+f"((cc)[1]), "+f"((cc)[2]), "+f"((cc)[3])                \
        : "r"((aa)[0]), "r"((aa)[1]), "r"((aa)[2]), "r"((aa)[3]),                   \
          "r"((bb)[0]), "r"((bb)[1]))

// dynamic smem layout for the GEMM (K-tile 64, rows padded to 72 halves = 144B)
#define GA_H 0
#define GA_L 18432
#define GB_H 36864
#define GB_L 55296
#define G_SSRED 73728
#define G_SMEM_TOTAL 74240
#define ROWP 72

// ---------------- HMMA GEMM, K-tile 64, pre-split operands (R7 staging style) ----------------
// C(half)[M,256] = A[M,K] @ Bt[256,K]^T, fp16 hi/lo 3-term;
// fused ssOut[r] += sum_c C[r,c]*sv[c]. Separate launch per direction.
__global__ void __launch_bounds__(256) gemm_f16x3_kernel(const __half* __restrict__ Ahg,
                                                         const __half* __restrict__ Alg,
                                                         const __half* __restrict__ Bhg,
                                                         const __half* __restrict__ Blg,
                                                         __half* __restrict__ C,
                                                         int M, int N, int K,
                                                         const float* __restrict__ sv,
                                                         float* __restrict__ ssOut) {
    extern __shared__ char smc[];
    __half* Ah = (__half*)(smc + GA_H);
    __half* Al = (__half*)(smc + GA_L);
    __half* Bh = (__half*)(smc + GB_H);
    __half* Bl = (__half*)(smc + GB_L);
    float* ssred = (float*)(smc + G_SSRED);

    int tid = threadIdx.x;
    int warp = tid >> 5, lane = tid & 31;
    int g = lane >> 2, tg = lane & 3;
    int wm = warp >> 2, wn = warp & 3;
    int bm = blockIdx.x * 128, bn = blockIdx.y * 128;

    float c[4][4][4] = {};

    for (int k0 = 0; k0 < K; k0 += 64) {
        // stage 64-wide k-tile: 1024 uint4 per array, 4 per thread per array
#pragma unroll
        for (int j = 0; j < 4; j++) {
            int idx = tid + j * 256;
            int row = idx >> 3, q = idx & 7;       // 8 uint4 (64 halves) per row
            uint4 vh = make_uint4(0, 0, 0, 0), vl = make_uint4(0, 0, 0, 0);
            int gr = bm + row;
            if (gr < M) {
                vh = *(const uint4*)(Ahg + (size_t)gr * K + k0 + q * 8);
                vl = *(const uint4*)(Alg + (size_t)gr * K + k0 + q * 8);
            }
            *(uint4*)&Ah[row * ROWP + q * 8] = vh;
            *(uint4*)&Al[row * ROWP + q * 8] = vl;
            uint4 wh = *(const uint4*)(Bhg + (size_t)(bn + row) * K + k0 + q * 8);
            uint4 wl = *(const uint4*)(Blg + (size_t)(bn + row) * K + k0 + q * 8);
            *(uint4*)&Bh[row * ROWP + q * 8] = wh;
            *(uint4*)&Bl[row * ROWP + q * 8] = wl;
        }
        __syncthreads();

#pragma unroll
        for (int ks = 0; ks < 4; ks++) {
            int kc = ks * 16 + tg * 2;
            unsigned ah[4][4], al[4][4], bh[4][2], bl[4][2];
#pragma unroll
            for (int mt = 0; mt < 4; mt++) {
                int r = wm * 64 + mt * 16 + g;
                ah[mt][0] = *(const unsigned*)&Ah[r * ROWP + kc];
                ah[mt][1] = *(const unsigned*)&Ah[(r + 8) * ROWP + kc];
                ah[mt][2] = *(const unsigned*)&Ah[r * ROWP + kc + 8];
                ah[mt][3] = *(const unsigned*)&Ah[(r + 8) * ROWP + kc + 8];
                al[mt][0] = *(const unsigned*)&Al[r * ROWP + kc];
                al[mt][1] = *(const unsigned*)&Al[(r + 8) * ROWP + kc];
                al[mt][2] = *(const unsigned*)&Al[r * ROWP + kc + 8];
                al[mt][3] = *(const unsigned*)&Al[(r + 8) * ROWP + kc + 8];
            }
#pragma unroll
            for (int nt = 0; nt < 4; nt++) {
                int n = wn * 32 + nt * 8 + g;
                bh[nt][0] = *(const unsigned*)&Bh[n * ROWP + kc];
                bh[nt][1] = *(const unsigned*)&Bh[n * ROWP + kc + 8];
                bl[nt][0] = *(const unsigned*)&Bl[n * ROWP + kc];
                bl[nt][1] = *(const unsigned*)&Bl[n * ROWP + kc + 8];
            }
#pragma unroll
            for (int mt = 0; mt < 4; mt++)
#pragma unroll
                for (int nt = 0; nt < 4; nt++) {
                    MMA_F16(c[mt][nt], ah[mt], bl[nt]);
                    MMA_F16(c[mt][nt], al[mt], bh[nt]);
                    MMA_F16(c[mt][nt], ah[mt], bh[nt]);
                }
        }
        __syncthreads();
    }

    // ss: per-row dot of C with sv
    if (tid < 128) ssred[tid] = 0.f;
    __syncthreads();
#pragma unroll
    for (int mt = 0; mt < 4; mt++) {
        float p0 = 0.f, p1 = 0.f;
#pragma unroll
        for (int nt = 0; nt < 4; nt++) {
            int col0 = bn + wn * 32 + nt * 8 + tg * 2;
            float2 sva = __ldg((const float2*)sv + (col0 >> 1));
            p0 += c[mt][nt][0] * sva.x + c[mt][nt][1] * sva.y;
            p1 += c[mt][nt][2] * sva.x + c[mt][nt][3] * sva.y;
        }
        p0 += __shfl_xor_sync(0xffffffffu, p0, 1);
        p0 += __shfl_xor_sync(0xffffffffu, p0, 2);
        p1 += __shfl_xor_sync(0xffffffffu, p1, 1);
        p1 += __shfl_xor_sync(0xffffffffu, p1, 2);
        if (tg == 0) {
            int rl = wm * 64 + mt * 16 + g;
            atomicAdd(&ssred[rl], p0);
            atomicAdd(&ssred[rl + 8], p1);
        }
    }
    __syncthreads();
    if (tid < 128) {
        int row = bm + tid;
        if (row < M) atomicAdd(ssOut + row, ssred[tid]);
    }

    // C store (fp16)
#pragma unroll
    for (int mt = 0; mt < 4; mt++) {
        int r0 = bm + wm * 64 + mt * 16 + g;
#pragma unroll
        for (int nt = 0; nt < 4; nt++) {
            int cc = bn + wn * 32 + nt * 8 + tg * 2;
            __half2 p0 = __floats2half2_rn(c[mt][nt][0], c[mt][nt][1]);
            __half2 p1 = __floats2half2_rn(c[mt][nt][2], c[mt][nt][3]);
            if (r0 < M)     *(__half2*)(C + (size_t)r0 * N + cc) = p0;
            if (r0 + 8 < M) *(__half2*)(C + (size_t)(r0 + 8) * N + cc) = p1;
        }
    }
}

// ---------------- transpose + split weights ----------------
__global__ void transpose2split_kernel(const float* __restrict__ W0,
                                       __half* __restrict__ T0h, __half* __restrict__ T0l,
                                       const float* __restrict__ W1,
                                       __half* __restrict__ T1h, __half* __restrict__ T1l,
                                       int K, int N) {
    __shared__ float t[32][33];
    const float* W = blockIdx.z ? W1 : W0;
    __half* Th = blockIdx.z ? T1h : T0h;
    __half* Tl = blockIdx.z ? T1l : T0l;
    int n0 = blockIdx.x * 32, k0 = blockIdx.y * 32;
#pragma unroll
    for (int i = 0; i < 4; i++) {
        int k = k0 + threadIdx.y + i * 8;
        t[threadIdx.y + i * 8][threadIdx.x] = W[(size_t)k * N + n0 + threadIdx.x];
    }
    __syncthreads();
#pragma unroll
    for (int i = 0; i < 4; i++) {
        int n = n0 + threadIdx.y + i * 8;
        float v = t[threadIdx.x][threadIdx.y + i * 8];
        float hv = __uint_as_float(__float_as_uint(v) & 0xFFFFE000u);
        Th[(size_t)n * K + k0 + threadIdx.x] = __float2half_rn(hv);
        Tl[(size_t)n * K + k0 + threadIdx.x] = __float2half_rn(v - hv);
    }
}

// ---------------- layer-1 X split (K=128) + dd dot ----------------
__global__ void splitX_kernel(const float* __restrict__ X,
                              __half* __restrict__ Xh, __half* __restrict__ Xl,
                              const float* __restrict__ dv, float* __restrict__ dd,
                              int M) {
    int w = (blockIdx.x * blockDim.x + threadIdx.x) >> 5;
    int lane = threadIdx.x & 31;
    if (w >= M) return;
    float4 v = *(const float4*)(X + (size_t)w * 128 + lane * 4);
    float4 dvv = __ldg((const float4*)dv + lane);
    float acc = v.x * dvv.x + v.y * dvv.y + v.z * dvv.z + v.w * dvv.w;
    split_store4(v, Xh + (size_t)w * 128 + lane * 4, Xl + (size_t)w * 128 + lane * 4);
#pragma unroll
    for (int o = 16; o; o >>= 1) acc += __shfl_xor_sync(0xffffffffu, acc, o);
    if (lane == 0) dd[w] = acc;
}

// ---------------- small-N GEMM (layer 3): X from hi+lo halves, fused ss ----------------
__global__ void __launch_bounds__(512) gemm_n16_kernel(const __half* __restrict__ Xh,
                                                       const __half* __restrict__ Xl,
                                                       const float* __restrict__ W,
                                                       float* __restrict__ H, int M,
                                                       const float* __restrict__ sv,
                                                       float* __restrict__ ssOut) {
    __shared__ float Ws[256 * 16];
    __shared__ float Xs[32 * 256];
    int tid = threadIdx.x;
    int row0 = blockIdx.x * 32;
    for (int i = tid; i < 256 * 16 / 4; i += 512)
        *(float4*)&Ws[i * 4] = *(const float4*)(W + i * 4);
#pragma unroll
    for (int i = 0; i < 4; i++) {
        int lin = tid + i * 512;
        int r = lin / 64;
        int c4 = lin % 64;
        float4 v = make_float4(0.f, 0.f, 0.f, 0.f);
        if (row0 + r < M) {
            uint2 vh = *(const uint2*)(Xh + (size_t)(row0 + r) * 256 + c4 * 4);
            uint2 vl = *(const uint2*)(Xl + (size_t)(row0 + r) * 256 + c4 * 4);
            const __half2* ph = (const __half2*)&vh;
            const __half2* pl = (const __half2*)&vl;
            float2 a0 = __half22float2(ph[0]), a1 = __half22float2(ph[1]);
            float2 b0 = __half22float2(pl[0]), b1 = __half22float2(pl[1]);
            v = make_float4(a0.x + b0.x, a0.y + b0.y, a1.x + b1.x, a1.y + b1.y);
        }
        *(float4*)&Xs[r * 256 + c4 * 4] = v;
    }
    __syncthreads();

    int r = tid / 16, c = tid % 16;
    float acc = 0.f;
#pragma unroll 8
    for (int k = 0; k < 256; k++) acc += Xs[r * 256 + k] * Ws[k * 16 + c];

    float sp = acc * __ldg(sv + c);
    sp += __shfl_xor_sync(0xffffffffu, sp, 1);
    sp += __shfl_xor_sync(0xffffffffu, sp, 2);
    sp += __shfl_xor_sync(0xffffffffu, sp, 4);
    sp += __shfl_xor_sync(0xffffffffu, sp, 8);
    if (row0 + r < M) {
        if ((tid & 15) == 0) ssOut[row0 + r] = sp;
        H[(size_t)(row0 + r) * 16 + c] = acc;
    }
}

// ---------------- fused dual W@a ----------------
__global__ void wv2_kernel(const float* __restrict__ W0, const float* __restrict__ a0,
                           float* __restrict__ o0,
                           const float* __restrict__ W1, const float* __restrict__ a1,
                           float* __restrict__ o1, int Fin, int Fout) {
    const float* W = blockIdx.y ? W1 : W0;
    const float* a = blockIdx.y ? a1 : a0;
    float* o = blockIdx.y ? o1 : o0;
    int w = (blockIdx.x * blockDim.x + threadIdx.x) >> 5;
    int lane = threadIdx.x & 31;
    if (w >= Fin) return;
    float s = 0.f;
    for (int j = lane; j < Fout; j += 32) s += W[(size_t)w * Fout + j] * a[j];
    for (int o2 = 16; o2; o2 >>= 1) s += __shfl_down_sync(0xffffffffu, s, o2);
    if (lane == 0) o[w] = s;
}

// ---------------- concatenated 2-direction CSR build ----------------
__global__ void hist2_kernel(const int* __restrict__ eab, const int* __restrict__ eba,
                             int* __restrict__ cnt) {
    int e = blockIdx.x * blockDim.x + threadIdx.x;
    if (e < NEDGE) atomicAdd(&cnt[eab[NEDGE + e]], 1);
    else if (e < 2 * NEDGE) atomicAdd(&cnt[NB + eba[NEDGE + e - NEDGE]], 1);
}

__global__ void scan1_kernel(const int* __restrict__ cnt, int* __restrict__ rowptr,
                             int* __restrict__ bsum, int n) {
    __shared__ int sh[1024];
    int i = blockIdx.x * 1024 + threadIdx.x;
    int v = (i < n) ? cnt[i] : 0;
    sh[threadIdx.x] = v;
    __syncthreads();
    for (int off = 1; off < 1024; off <<= 1) {
        int t = (threadIdx.x >= off) ? sh[threadIdx.x - off] : 0;
        __syncthreads();
        sh[threadIdx.x] += t;
        __syncthreads();
    }
    if (i < n) rowptr[i + 1] = sh[threadIdx.x];
    if (threadIdx.x == 1023) bsum[blockIdx.x] = sh[1023];
}

__global__ void scan2_kernel(int* __restrict__ bsum, int nb) {
    __shared__ int sh[128];
    int t = threadIdx.x;
    int v = (t < nb) ? bsum[t] : 0;
    sh[t] = v;
    __syncthreads();
    for (int off = 1; off < 128; off <<= 1) {
        int u = (t >= off) ? sh[t - off] : 0;
        __syncthreads();
        sh[t] += u;
        __syncthreads();
    }
    if (t < nb) bsum[t] = sh[t] - v;
}

__global__ void scan3_kernel(int* __restrict__ rowptr, const int* __restrict__ bsum, int n) {
    int i = blockIdx.x * 1024 + threadIdx.x;
    if (i < n) rowptr[i + 1] += bsum[blockIdx.x];
    if (i == 0) rowptr[0] = 0;
}

__global__ void scatter2_kernel(const int* __restrict__ eab, const int* __restrict__ eba,
                                const int* __restrict__ rowptr, int* __restrict__ fill,
                                int* __restrict__ sorted) {
    int e = blockIdx.x * blockDim.x + threadIdx.x;
    int s, seg;
    if (e < NEDGE) { s = eab[e]; seg = eab[NEDGE + e]; }
    else if (e < 2 * NEDGE) { int e2 = e - NEDGE; s = eba[e2]; seg = NB + eba[NEDGE + e2]; }
    else return;
    int p = rowptr[seg] + atomicAdd(&fill[seg], 1);
    sorted[p] = s;
}

// ---------------- fused GAT (FOUT=256): fp16 gather; writes split X + next dd ----------------
__global__ void __launch_bounds__(256) gat256h_kernel(const int* __restrict__ rowptr,
                                                      const int* __restrict__ ssrc,
                                                      const float* __restrict__ ss,
                                                      const float* __restrict__ dd,
                                                      const __half* __restrict__ H,
                                                      const float* __restrict__ bias,
                                                      __half* __restrict__ Xh,
                                                      __half* __restrict__ Xl,
                                                      const float* __restrict__ dvn,
                                                      float* __restrict__ ddn,
                                                      int ndst) {
    int w = (blockIdx.x * blockDim.x + threadIdx.x) >> 5;
    int lane = threadIdx.x & 31;
    if (w >= ndst) return;
    int b0 = rowptr[w], b1 = rowptr[w + 1];
    float ddv = dd[w];

    float mx = __int_as_float(0xff800000);
    for (int i = b0 + lane; i < b1; i += 32) {
        float v = __ldg(ss + ssrc[i]) + ddv;
        v = v > 0.f ? v : 0.2f * v;
        mx = fmaxf(mx, v);
    }
#pragma unroll
    for (int o = 16; o; o >>= 1) mx = fmaxf(mx, __shfl_xor_sync(0xffffffffu, mx, o));

    float acc[8] = {};
    float sum = 0.f;
    for (int base = b0; base < b1; base += 32) {
        int i = base + lane;
        float wgt = 0.f;
        int s = 0;
        if (i < b1) {
            s = ssrc[i];
            float v = __ldg(ss + s) + ddv;
            v = v > 0.f ? v : 0.2f * v;
            wgt = __expf(v - mx);
        }
        sum += wgt;
        int nn = min(32, b1 - base);
        for (int t = 0; t < nn; t++) {
            float wt = __shfl_sync(0xffffffffu, wgt, t);
            int st = __shfl_sync(0xffffffffu, s, t);
            uint4 u = __ldg((const uint4*)(H + (size_t)st * 256) + lane);
            const __half2* hh = (const __half2*)&u;
#pragma unroll
            for (int j = 0; j < 4; j++) {
                float2 f = __half22float2(hh[j]);
                acc[2 * j]     += wt * f.x;
                acc[2 * j + 1] += wt * f.y;
            }
        }
    }
#pragma unroll
    for (int o = 16; o; o >>= 1) sum += __shfl_xor_sync(0xffffffffu, sum, o);
    float inv = 1.f / (sum + 1e-16f);

    float4 bb0 = __ldg((const float4*)bias + lane * 2);
    float4 bb1 = __ldg((const float4*)bias + lane * 2 + 1);
    float4 o0, o1;
    o0.x = fmaxf(acc[0] * inv + bb0.x, 0.f); o0.y = fmaxf(acc[1] * inv + bb0.y, 0.f);
    o0.z = fmaxf(acc[2] * inv + bb0.z, 0.f); o0.w = fmaxf(acc[3] * inv + bb0.w, 0.f);
    o1.x = fmaxf(acc[4] * inv + bb1.x, 0.f); o1.y = fmaxf(acc[5] * inv + bb1.y, 0.f);
    o1.z = fmaxf(acc[6] * inv + bb1.z, 0.f); o1.w = fmaxf(acc[7] * inv + bb1.w, 0.f);

    union U4 { __half2 h2[4]; uint4 u; };
    U4 uh, ul;
    split2(o0.x, o0.y, &uh.h2[0], &ul.h2[0]);
    split2(o0.z, o0.w, &uh.h2[1], &ul.h2[1]);
    split2(o1.x, o1.y, &uh.h2[2], &ul.h2[2]);
    split2(o1.z, o1.w, &uh.h2[3], &ul.h2[3]);
    *(uint4*)(Xh + (size_t)w * 256 + lane * 8) = uh.u;
    *(uint4*)(Xl + (size_t)w * 256 + lane * 8) = ul.u;

    float4 dva = __ldg((const float4*)dvn + lane * 2);
    float4 dvb = __ldg((const float4*)dvn + lane * 2 + 1);
    float dq = o0.x * dva.x + o0.y * dva.y + o0.z * dva.z + o0.w * dva.w
             + o1.x * dvb.x + o1.y * dvb.y + o1.z * dvb.z + o1.w * dvb.w;
#pragma unroll
    for (int o = 16; o; o >>= 1) dq += __shfl_xor_sync(0xffffffffu, dq, o);
    if (lane == 0) ddn[w] = dq;
}

// ---------------- fused GAT (FOUT=16, final layer, fp32 H) ----------------
__global__ void __launch_bounds__(256) gat16_kernel(const int* __restrict__ rowptr,
                                                    const int* __restrict__ ssrc,
                                                    const float* __restrict__ ss,
                                                    const float* __restrict__ dd,
                                                    const float* __restrict__ H,
                                                    const float* __restrict__ bias,
                                                    float* __restrict__ out, int ndst) {
    int w = (blockIdx.x * blockDim.x + threadIdx.x) >> 5;
    int lane = threadIdx.x & 31;
    if (w >= ndst) return;
    int b0 = rowptr[w], b1 = rowptr[w + 1];
    float ddv = dd[w];
    int half = lane >> 4, fl = lane & 15;

    float mx = __int_as_float(0xff800000);
    for (int i = b0 + lane; i < b1; i += 32) {
        float v = __ldg(ss + ssrc[i]) + ddv;
        v = v > 0.f ? v : 0.2f * v;
        mx = fmaxf(mx, v);
    }
#pragma unroll
    for (int o = 16; o; o >>= 1) mx = fmaxf(mx, __shfl_xor_sync(0xffffffffu, mx, o));

    float acc = 0.f;
    float sum = 0.f;
    for (int base = b0; base < b1; base += 32) {
        int i = base + lane;
        float wgt = 0.f;
        int s = 0;
        if (i < b1) {
            s = ssrc[i];
            float v = __ldg(ss + s) + ddv;
            v = v > 0.f ? v : 0.2f * v;
            wgt = __expf(v - mx);
        }
        sum += wgt;
        int nn = min(32, b1 - base);
        for (int t = 0; t < nn; t += 2) {
            int tt = t + half;
            float wt = __shfl_sync(0xffffffffu, wgt, tt);
            int st = __shfl_sync(0xffffffffu, s, tt);
            if (tt < nn) acc += wt * __ldg(H + (size_t)st * 16 + fl);
        }
    }
#pragma unroll
    for (int o = 16; o; o >>= 1) sum += __shfl_xor_sync(0xffffffffu, sum, o);
    acc += __shfl_xor_sync(0xffffffffu, acc, 16);
    float inv = 1.f / (sum + 1e-16f);
    if (lane < 16)
        out[(size_t)w * 16 + lane] = acc * inv + __ldg(bias + lane);
}

// ---------------- readout ----------------
__global__ void sumrows16_kernel(const float* __restrict__ xb, const int* __restrict__ dstidx,
                                 float* __restrict__ out16, int L) {
    __shared__ float sh[16];
    if (threadIdx.x < 16) sh[threadIdx.x] = 0.f;
    __syncthreads();
    float loc[16];
#pragma unroll
    for (int k = 0; k < 16; k++) loc[k] = 0.f;
    for (int t = blockIdx.x * blockDim.x + threadIdx.x; t < L; t += gridDim.x * blockDim.x) {
        const float* row = xb + (size_t)dstidx[t] * 16;
#pragma unroll
        for (int k = 0; k < 16; k++) loc[k] += row[k];
    }
#pragma unroll
    for (int k = 0; k < 16; k++) atomicAdd(&sh[k], loc[k]);
    __syncthreads();
    if (threadIdx.x < 16) atomicAdd(&out16[threadIdx.x], sh[threadIdx.x]);
}

__global__ void pred_kernel(const float* __restrict__ xa, const int* __restrict__ srcidx,
                            const float* __restrict__ sum16, float* __restrict__ pred, int L) {
    int t = blockIdx.x * blockDim.x + threadIdx.x;
    if (t >= L) return;
    const float* row = xa + (size_t)srcidx[t] * 16;
    float s = 0.f;
#pragma unroll
    for (int k = 0; k < 16; k++) s += row[k] * __ldg(sum16 + k);
    pred[t] = s;
}

// ---------------- host orchestration ----------------
static inline int cdiv(int a, int b) { return (a + b - 1) / b; }

extern "C" void kernel_launch(void* const* d_in, const int* in_sizes, int n_in,
                              void* d_out, int out_size) {
    const float* xAin = (const float*)d_in[0];
    const float* xBin = (const float*)d_in[1];
    const int* ei_ab = (const int*)d_in[2];
    const int* ei_ba = (const int*)d_in[3];
    const int* srcI = (const int*)d_in[4];
    const int* dstI = (const int*)d_in[5];

    const float* Wab[3]  = {(const float*)d_in[6],  (const float*)d_in[14], (const float*)d_in[22]};
    const float* asab[3] = {(const float*)d_in[7],  (const float*)d_in[15], (const float*)d_in[23]};
    const float* adab[3] = {(const float*)d_in[8],  (const float*)d_in[16], (const float*)d_in[24]};
    const float* bab[3]  = {(const float*)d_in[9],  (const float*)d_in[17], (const float*)d_in[25]};
    const float* Wba[3]  = {(const float*)d_in[10], (const float*)d_in[18], (const float*)d_in[26]};
    const float* asba[3] = {(const float*)d_in[11], (const float*)d_in[19], (const float*)d_in[27]};
    const float* adba[3] = {(const float*)d_in[12], (const float*)d_in[20], (const float*)d_in[28]};
    const float* bba[3]  = {(const float*)d_in[13], (const float*)d_in[21], (const float*)d_in[29]};

    float* out = (float*)d_out;
    float* pred = out;
    float* xaOut = out + LPRED;
    float* xbOut = xaOut + (size_t)NA * 16;

    float* F = nullptr;
    int* I = nullptr;
    cudaGetSymbolAddress((void**)&F, g_fpool);
    cudaGetSymbolAddress((void**)&I, g_ipool);

    cudaFuncSetAttribute(gemm_f16x3_kernel, cudaFuncAttributeMaxDynamicSharedMemorySize,
                         G_SMEM_TOTAL);

    __half* XAH = (__half*)(F + OFF_XAH);
    __half* XAL = (__half*)(F + OFF_XAL);
    __half* XBH = (__half*)(F + OFF_XBH);
    __half* XBL = (__half*)(F + OFF_XBL);
    float* HABf = F + OFF_HAB;
    float* HBAf = F + OFF_HBA;
    __half* HABh = (__half*)(F + OFF_HAB);
    __half* HBAh = (__half*)(F + OFF_HBA);
    float* SSAB = F + OFF_SSAB;
    float* SSBA = F + OFF_SSBA;
    float* DDAB = F + OFF_DDAB;
    float* DDBA = F + OFF_DDBA;
    float* SV = F + OFF_SV;
    float* SUM16 = F + OFF_SUM16;
    __half* WTABH = (__half*)(F + OFF_WTABH);
    __half* WTABL = (__half*)(F + OFF_WTABL);
    __half* WTBAH = (__half*)(F + OFF_WTBAH);
    __half* WTBAL = (__half*)(F + OFF_WTBAL);

    int* RP2 = I + IOFF_RP2;
    int* CNT2 = I + IOFF_CNT2;
    int* FILL2 = I + IOFF_FILL2;
    int* SRT = I + IOFF_SRT;
    int* BSUM = I + IOFF_BSUM;

    const int FinL[3] = {128, 256, 256};
    const int FoutL[3] = {256, 256, 16};

    // ---- all dv projections upfront: SV + l*512 {+0: ab, +256: ba} ----
    for (int l = 0; l < 3; l++)
        wv2_kernel<<<dim3(cdiv(FinL[l], 8), 2), 256>>>(
            Wab[l], adab[l], SV + l * 512, Wba[l], adba[l], SV + l * 512 + 256,
            FinL[l], FoutL[l]);

    // ---- concatenated CSR build ----
    const int NSEG = NA + NB;
    const int nScanBlk = cdiv(NSEG, 1024);
    cudaMemsetAsync(CNT2, 0, NSEG * sizeof(int), 0);
    hist2_kernel<<<cdiv(2 * NEDGE, 256), 256>>>(ei_ab, ei_ba, CNT2);
    scan1_kernel<<<nScanBlk, 1024>>>(CNT2, RP2, BSUM, NSEG);
    scan2_kernel<<<1, 128>>>(BSUM, nScanBlk);
    scan3_kernel<<<nScanBlk, 1024>>>(RP2, BSUM, NSEG);
    cudaMemsetAsync(FILL2, 0, NSEG * sizeof(int), 0);
    scatter2_kernel<<<cdiv(2 * NEDGE, 256), 256>>>(ei_ab, ei_ba, RP2, FILL2, SRT);

    // ---- layer-1 X split + dd ----
    splitX_kernel<<<cdiv(NA, 8), 256>>>(xAin, XAH, XAL, SV + 256, DDBA, NA);
    splitX_kernel<<<cdiv(NB, 8), 256>>>(xBin, XBH, XBL, SV + 0, DDAB, NB);

    for (int l = 0; l < 3; l++) {
        int Fin = FinL[l];

        if (l < 2) {
            cudaMemsetAsync(SSAB, 0, 2 * NA * sizeof(float), 0);  // SSAB + SSBA
            transpose2split_kernel<<<dim3(256 / 32, Fin / 32, 2), dim3(32, 8)>>>(
                Wab[l], WTABH, WTABL, Wba[l], WTBAH, WTBAL, Fin, 256);
            // separate launches per direction (R7 structure — empirically fastest)
            gemm_f16x3_kernel<<<dim3(cdiv(NA, 128), 2), 256, G_SMEM_TOTAL>>>(
                XAH, XAL, WTABH, WTABL, HABh, NA, 256, Fin, asab[l], SSAB);
            gemm_f16x3_kernel<<<dim3(cdiv(NB, 128), 2), 256, G_SMEM_TOTAL>>>(
                XBH, XBL, WTBAH, WTBAL, HBAh, NB, 256, Fin, asba[l], SSBA);

            gat256h_kernel<<<cdiv(NB, 8), 256>>>(RP2, SRT, SSAB, DDAB, HABh, bab[l],
                                                 XBH, XBL, SV + (l + 1) * 512, DDAB, NB);
            gat256h_kernel<<<cdiv(NA, 8), 256>>>(RP2 + NB, SRT, SSBA, DDBA, HBAh, bba[l],
                                                 XAH, XAL, SV + (l + 1) * 512 + 256, DDBA, NA);
        } else {
            gemm_n16_kernel<<<cdiv(NA, 32), 512>>>(XAH, XAL, Wab[l], HABf, NA, asab[l], SSAB);
            gemm_n16_kernel<<<cdiv(NB, 32), 512>>>(XBH, XBL, Wba[l], HBAf, NB, asba[l], SSBA);

            gat16_kernel<<<cdiv(NB, 8), 256>>>(RP2, SRT, SSAB, DDAB, HABf, bab[l], xbOut, NB);
            gat16_kernel<<<cdiv(NA, 8), 256>>>(RP2 + NB, SRT, SSBA, DDBA, HBAf, bba[l], xaOut, NA);
        }
    }

    // ---- readout ----
    cudaMemsetAsync(SUM16, 0, 16 * sizeof(float), 0);
    sumrows16_kernel<<<256, 256>>>(xbOut, dstI, SUM16, LPRED);
    pred_kernel<<<cdiv(LPRED, 256), 256>>>(xaOut, srcI, SUM16, pred, LPRED);
}

// round 13
// speedup vs baseline: 1.1474x; 1.0012x over previous
#include <cuda_runtime.h>
#include <cuda_fp16.h>
#include <math.h>
#include <stdint.h>

#define NA 50000
#define NB 50000
#define NEDGE 1000000
#define LPRED 100000

// ---------------- device scratch pools ----------------
#define OFF_XAH   0u
#define OFF_XAL   6400000u
#define OFF_XBH   12800000u
#define OFF_XBL   19200000u
#define OFF_HAB   25600000u
#define OFF_HBA   38400000u
#define OFF_SSAB  51200000u
#define OFF_SSBA  51250000u
#define OFF_DDAB  51300000u
#define OFF_DDBA  51350000u
#define OFF_SV    51400000u             // 6*256 dv vectors (padded 2048)
#define OFF_SUM16 51402048u
#define OFF_WTABH 51402064u
#define OFF_WTABL 51434832u
#define OFF_WTBAH 51467600u
#define OFF_WTBAL 51500368u
#define FPOOL_N   51533136u

#define IOFF_RP2   0u
#define IOFF_CNT2  100001u
#define IOFF_FILL2 200001u
#define IOFF_SRT   300001u
#define IOFF_BSUM  2300001u
#define IPOOL_N    2300129u

static __device__ float g_fpool[FPOOL_N];
static __device__ int   g_ipool[IPOOL_N];

// ---------------- fp16 hi/lo split helpers ----------------
__device__ __forceinline__ void split2(float x, float y, __half2* ph, __half2* pl) {
    float hx = __uint_as_float(__float_as_uint(x) & 0xFFFFE000u);
    float hy = __uint_as_float(__float_as_uint(y) & 0xFFFFE000u);
    *ph = __halves2half2(__float2half_rn(hx), __float2half_rn(hy));
    *pl = __halves2half2(__float2half_rn(x - hx), __float2half_rn(y - hy));
}

__device__ __forceinline__ void split_store4(float4 v, __half* ph, __half* pl) {
    __half2 h01, l01, h23, l23;
    split2(v.x, v.y, &h01, &l01);
    split2(v.z, v.w, &h23, &l23);
    *(__half2*)(ph)     = h01;
    *(__half2*)(ph + 2) = h23;
    *(__half2*)(pl)     = l01;
    *(__half2*)(pl + 2) = l23;
}

#define MMA_F16(cc, aa, bb)                                                         \
    asm volatile(                                                                   \
        "mma.sync.aligned.m16n8k16.row.col.f32.f16.f16.f32 "                        \
        "{%0,%1,%2,%3},{%4,%5,%6,%7},{%8,%9},{%0,%1,%2,%3};\n"                      \
        : "+f"((cc)[0]), "+f"((cc)[1]), "+f"((cc)[2]), "+f"((cc)[3])                \
        : "r"((aa)[0]), "r"((aa)[1]), "r"((aa)[2]), "r"((aa)[3]),                   \
          "r"((bb)[0]), "r"((bb)[1]))

// dynamic smem layout for the GEMM (K-tile 64, rows padded to 72 halves = 144B)
#define GA_H 0
#define GA_L 18432
#define GB_H 36864
#define GB_L 55296
#define G_SSRED 73728
#define G_SMEM_TOTAL 74240
#define ROWP 72

// ---------------- HMMA GEMM, K-tile 64, pre-split operands ----------------
__global__ void __launch_bounds__(256) gemm_f16x3_kernel(const __half* __restrict__ Ahg,
                                                         const __half* __restrict__ Alg,
                                                         const __half* __restrict__ Bhg,
                                                         const __half* __restrict__ Blg,
                                                         __half* __restrict__ C,
                                                         int M, int N, int K,
                                                         const float* __restrict__ sv,
                                                         float* __restrict__ ssOut) {
    extern __shared__ char smc[];
    __half* Ah = (__half*)(smc + GA_H);
    __half* Al = (__half*)(smc + GA_L);
    __half* Bh = (__half*)(smc + GB_H);
    __half* Bl = (__half*)(smc + GB_L);
    float* ssred = (float*)(smc + G_SSRED);

    int tid = threadIdx.x;
    int warp = tid >> 5, lane = tid & 31;
    int g = lane >> 2, tg = lane & 3;
    int wm = warp >> 2, wn = warp & 3;
    int bm = blockIdx.x * 128, bn = blockIdx.y * 128;

    float c[4][4][4] = {};

    for (int k0 = 0; k0 < K; k0 += 64) {
#pragma unroll
        for (int j = 0; j < 4; j++) {
            int idx = tid + j * 256;
            int row = idx >> 3, q = idx & 7;
            uint4 vh = make_uint4(0, 0, 0, 0), vl = make_uint4(0, 0, 0, 0);
            int gr = bm + row;
            if (gr < M) {
                vh = *(const uint4*)(Ahg + (size_t)gr * K + k0 + q * 8);
                vl = *(const uint4*)(Alg + (size_t)gr * K + k0 + q * 8);
            }
            *(uint4*)&Ah[row * ROWP + q * 8] = vh;
            *(uint4*)&Al[row * ROWP + q * 8] = vl;
            uint4 wh = *(const uint4*)(Bhg + (size_t)(bn + row) * K + k0 + q * 8);
            uint4 wl = *(const uint4*)(Blg + (size_t)(bn + row) * K + k0 + q * 8);
            *(uint4*)&Bh[row * ROWP + q * 8] = wh;
            *(uint4*)&Bl[row * ROWP + q * 8] = wl;
        }
        __syncthreads();

#pragma unroll
        for (int ks = 0; ks < 4; ks++) {
            int kc = ks * 16 + tg * 2;
            unsigned ah[4][4], al[4][4], bh[4][2], bl[4][2];
#pragma unroll
            for (int mt = 0; mt < 4; mt++) {
                int r = wm * 64 + mt * 16 + g;
                ah[mt][0] = *(const unsigned*)&Ah[r * ROWP + kc];
                ah[mt][1] = *(const unsigned*)&Ah[(r + 8) * ROWP + kc];
                ah[mt][2] = *(const unsigned*)&Ah[r * ROWP + kc + 8];
                ah[mt][3] = *(const unsigned*)&Ah[(r + 8) * ROWP + kc + 8];
                al[mt][0] = *(const unsigned*)&Al[r * ROWP + kc];
                al[mt][1] = *(const unsigned*)&Al[(r + 8) * ROWP + kc];
                al[mt][2] = *(const unsigned*)&Al[r * ROWP + kc + 8];
                al[mt][3] = *(const unsigned*)&Al[(r + 8) * ROWP + kc + 8];
            }
#pragma unroll
            for (int nt = 0; nt < 4; nt++) {
                int n = wn * 32 + nt * 8 + g;
                bh[nt][0] = *(const unsigned*)&Bh[n * ROWP + kc];
                bh[nt][1] = *(const unsigned*)&Bh[n * ROWP + kc + 8];
                bl[nt][0] = *(const unsigned*)&Bl[n * ROWP + kc];
                bl[nt][1] = *(const unsigned*)&Bl[n * ROWP + kc + 8];
            }
#pragma unroll
            for (int mt = 0; mt < 4; mt++)
#pragma unroll
                for (int nt = 0; nt < 4; nt++) {
                    MMA_F16(c[mt][nt], ah[mt], bl[nt]);
                    MMA_F16(c[mt][nt], al[mt], bh[nt]);
                    MMA_F16(c[mt][nt], ah[mt], bh[nt]);
                }
        }
        __syncthreads();
    }

    if (tid < 128) ssred[tid] = 0.f;
    __syncthreads();
#pragma unroll
    for (int mt = 0; mt < 4; mt++) {
        float p0 = 0.f, p1 = 0.f;
#pragma unroll
        for (int nt = 0; nt < 4; nt++) {
            int col0 = bn + wn * 32 + nt * 8 + tg * 2;
            float2 sva = __ldg((const float2*)sv + (col0 >> 1));
            p0 += c[mt][nt][0] * sva.x + c[mt][nt][1] * sva.y;
            p1 += c[mt][nt][2] * sva.x + c[mt][nt][3] * sva.y;
        }
        p0 += __shfl_xor_sync(0xffffffffu, p0, 1);
        p0 += __shfl_xor_sync(0xffffffffu, p0, 2);
        p1 += __shfl_xor_sync(0xffffffffu, p1, 1);
        p1 += __shfl_xor_sync(0xffffffffu, p1, 2);
        if (tg == 0) {
            int rl = wm * 64 + mt * 16 + g;
            atomicAdd(&ssred[rl], p0);
            atomicAdd(&ssred[rl + 8], p1);
        }
    }
    __syncthreads();
    if (tid < 128) {
        int row = bm + tid;
        if (row < M) atomicAdd(ssOut + row, ssred[tid]);
    }

#pragma unroll
    for (int mt = 0; mt < 4; mt++) {
        int r0 = bm + wm * 64 + mt * 16 + g;
#pragma unroll
        for (int nt = 0; nt < 4; nt++) {
            int cc = bn + wn * 32 + nt * 8 + tg * 2;
            __half2 p0 = __floats2half2_rn(c[mt][nt][0], c[mt][nt][1]);
            __half2 p1 = __floats2half2_rn(c[mt][nt][2], c[mt][nt][3]);
            if (r0 < M)     *(__half2*)(C + (size_t)r0 * N + cc) = p0;
            if (r0 + 8 < M) *(__half2*)(C + (size_t)(r0 + 8) * N + cc) = p1;
        }
    }
}

// ---------------- transpose + split weights ----------------
__global__ void transpose2split_kernel(const float* __restrict__ W0,
                                       __half* __restrict__ T0h, __half* __restrict__ T0l,
                                       const float* __restrict__ W1,
                                       __half* __restrict__ T1h, __half* __restrict__ T1l,
                                       int K, int N) {
    __shared__ float t[32][33];
    const float* W = blockIdx.z ? W1 : W0;
    __half* Th = blockIdx.z ? T1h : T0h;
    __half* Tl = blockIdx.z ? T1l : T0l;
    int n0 = blockIdx.x * 32, k0 = blockIdx.y * 32;
#pragma unroll
    for (int i = 0; i < 4; i++) {
        int k = k0 + threadIdx.y + i * 8;
        t[threadIdx.y + i * 8][threadIdx.x] = W[(size_t)k * N + n0 + threadIdx.x];
    }
    __syncthreads();
#pragma unroll
    for (int i = 0; i < 4; i++) {
        int n = n0 + threadIdx.y + i * 8;
        float v = t[threadIdx.x][threadIdx.y + i * 8];
        float hv = __uint_as_float(__float_as_uint(v) & 0xFFFFE000u);
        Th[(size_t)n * K + k0 + threadIdx.x] = __float2half_rn(hv);
        Tl[(size_t)n * K + k0 + threadIdx.x] = __float2half_rn(v - hv);
    }
}

// ---------------- layer-1 X split (K=128) + dd dot ----------------
__global__ void splitX_kernel(const float* __restrict__ X,
                              __half* __restrict__ Xh, __half* __restrict__ Xl,
                              const float* __restrict__ dv, float* __restrict__ dd,
                              int M) {
    int w = (blockIdx.x * blockDim.x + threadIdx.x) >> 5;
    int lane = threadIdx.x & 31;
    if (w >= M) return;
    float4 v = *(const float4*)(X + (size_t)w * 128 + lane * 4);
    float4 dvv = __ldg((const float4*)dv + lane);
    float acc = v.x * dvv.x + v.y * dvv.y + v.z * dvv.z + v.w * dvv.w;
    split_store4(v, Xh + (size_t)w * 128 + lane * 4, Xl + (size_t)w * 128 + lane * 4);
#pragma unroll
    for (int o = 16; o; o >>= 1) acc += __shfl_xor_sync(0xffffffffu, acc, o);
    if (lane == 0) dd[w] = acc;
}

// ---------------- small-N GEMM (layer 3) ----------------
__global__ void __launch_bounds__(512) gemm_n16_kernel(const __half* __restrict__ Xh,
                                                       const __half* __restrict__ Xl,
                                                       const float* __restrict__ W,
                                                       float* __restrict__ H, int M,
                                                       const float* __restrict__ sv,
                                                       float* __restrict__ ssOut) {
    __shared__ float Ws[256 * 16];
    __shared__ float Xs[32 * 256];
    int tid = threadIdx.x;
    int row0 = blockIdx.x * 32;
    for (int i = tid; i < 256 * 16 / 4; i += 512)
        *(float4*)&Ws[i * 4] = *(const float4*)(W + i * 4);
#pragma unroll
    for (int i = 0; i < 4; i++) {
        int lin = tid + i * 512;
        int r = lin / 64;
        int c4 = lin % 64;
        float4 v = make_float4(0.f, 0.f, 0.f, 0.f);
        if (row0 + r < M) {
            uint2 vh = *(const uint2*)(Xh + (size_t)(row0 + r) * 256 + c4 * 4);
            uint2 vl = *(const uint2*)(Xl + (size_t)(row0 + r) * 256 + c4 * 4);
            const __half2* ph = (const __half2*)&vh;
            const __half2* pl = (const __half2*)&vl;
            float2 a0 = __half22float2(ph[0]), a1 = __half22float2(ph[1]);
            float2 b0 = __half22float2(pl[0]), b1 = __half22float2(pl[1]);
            v = make_float4(a0.x + b0.x, a0.y + b0.y, a1.x + b1.x, a1.y + b1.y);
        }
        *(float4*)&Xs[r * 256 + c4 * 4] = v;
    }
    __syncthreads();

    int r = tid / 16, c = tid % 16;
    float acc = 0.f;
#pragma unroll 8
    for (int k = 0; k < 256; k++) acc += Xs[r * 256 + k] * Ws[k * 16 + c];

    float sp = acc * __ldg(sv + c);
    sp += __shfl_xor_sync(0xffffffffu, sp, 1);
    sp += __shfl_xor_sync(0xffffffffu, sp, 2);
    sp += __shfl_xor_sync(0xffffffffu, sp, 4);
    sp += __shfl_xor_sync(0xffffffffu, sp, 8);
    if (row0 + r < M) {
        if ((tid & 15) == 0) ssOut[row0 + r] = sp;
        H[(size_t)(row0 + r) * 16 + c] = acc;
    }
}

// ---------------- fused dual W@a ----------------
__global__ void wv2_kernel(const float* __restrict__ W0, const float* __restrict__ a0,
                           float* __restrict__ o0,
                           const float* __restrict__ W1, const float* __restrict__ a1,
                           float* __restrict__ o1, int Fin, int Fout) {
    const float* W = blockIdx.y ? W1 : W0;
    const float* a = blockIdx.y ? a1 : a0;
    float* o = blockIdx.y ? o1 : o0;
    int w = (blockIdx.x * blockDim.x + threadIdx.x) >> 5;
    int lane = threadIdx.x & 31;
    if (w >= Fin) return;
    float s = 0.f;
    for (int j = lane; j < Fout; j += 32) s += W[(size_t)w * Fout + j] * a[j];
    for (int o2 = 16; o2; o2 >>= 1) s += __shfl_down_sync(0xffffffffu, s, o2);
    if (lane == 0) o[w] = s;
}

// ---------------- concatenated 2-direction CSR build ----------------
__global__ void hist2_kernel(const int* __restrict__ eab, const int* __restrict__ eba,
                             int* __restrict__ cnt) {
    int e = blockIdx.x * blockDim.x + threadIdx.x;
    if (e < NEDGE) atomicAdd(&cnt[eab[NEDGE + e]], 1);
    else if (e < 2 * NEDGE) atomicAdd(&cnt[NB + eba[NEDGE + e - NEDGE]], 1);
}

__global__ void scan1_kernel(const int* __restrict__ cnt, int* __restrict__ rowptr,
                             int* __restrict__ bsum, int n) {
    __shared__ int sh[1024];
    int i = blockIdx.x * 1024 + threadIdx.x;
    int v = (i < n) ? cnt[i] : 0;
    sh[threadIdx.x] = v;
    __syncthreads();
    for (int off = 1; off < 1024; off <<= 1) {
        int t = (threadIdx.x >= off) ? sh[threadIdx.x - off] : 0;
        __syncthreads();
        sh[threadIdx.x] += t;
        __syncthreads();
    }
    if (i < n) rowptr[i + 1] = sh[threadIdx.x];
    if (threadIdx.x == 1023) bsum[blockIdx.x] = sh[1023];
}

__global__ void scan2_kernel(int* __restrict__ bsum, int nb) {
    __shared__ int sh[128];
    int t = threadIdx.x;
    int v = (t < nb) ? bsum[t] : 0;
    sh[t] = v;
    __syncthreads();
    for (int off = 1; off < 128; off <<= 1) {
        int u = (t >= off) ? sh[t - off] : 0;
        __syncthreads();
        sh[t] += u;
        __syncthreads();
    }
    if (t < nb) bsum[t] = sh[t] - v;
}

__global__ void scan3_kernel(int* __restrict__ rowptr, const int* __restrict__ bsum, int n) {
    int i = blockIdx.x * 1024 + threadIdx.x;
    if (i < n) rowptr[i + 1] += bsum[blockIdx.x];
    if (i == 0) rowptr[0] = 0;
}

__global__ void scatter2_kernel(const int* __restrict__ eab, const int* __restrict__ eba,
                                const int* __restrict__ rowptr, int* __restrict__ fill,
                                int* __restrict__ sorted) {
    int e = blockIdx.x * blockDim.x + threadIdx.x;
    int s, seg;
    if (e < NEDGE) { s = eab[e]; seg = eab[NEDGE + e]; }
    else if (e < 2 * NEDGE) { int e2 = e - NEDGE; s = eba[e2]; seg = NB + eba[NEDGE + e2]; }
    else return;
    int p = rowptr[seg] + atomicAdd(&fill[seg], 1);
    sorted[p] = s;
}

// ---------------- fused GAT (FOUT=256) ----------------
__global__ void __launch_bounds__(256) gat256h_kernel(const int* __restrict__ rowptr,
                                                      const int* __restrict__ ssrc,
                                                      const float* __restrict__ ss,
                                                      const float* __restrict__ dd,
                                                      const __half* __restrict__ H,
                                                      const float* __restrict__ bias,
                                                      __half* __restrict__ Xh,
                                                      __half* __restrict__ Xl,
                                                      const float* __restrict__ dvn,
                                                      float* __restrict__ ddn,
                                                      int ndst) {
    int w = (blockIdx.x * blockDim.x + threadIdx.x) >> 5;
    int lane = threadIdx.x & 31;
    if (w >= ndst) return;
    int b0 = rowptr[w], b1 = rowptr[w + 1];
    float ddv = dd[w];

    float mx = __int_as_float(0xff800000);
    for (int i = b0 + lane; i < b1; i += 32) {
        float v = __ldg(ss + ssrc[i]) + ddv;
        v = v > 0.f ? v : 0.2f * v;
        mx = fmaxf(mx, v);
    }
#pragma unroll
    for (int o = 16; o; o >>= 1) mx = fmaxf(mx, __shfl_xor_sync(0xffffffffu, mx, o));

    float acc[8] = {};
    float sum = 0.f;
    for (int base = b0; base < b1; base += 32) {
        int i = base + lane;
        float wgt = 0.f;
        int s = 0;
        if (i < b1) {
            s = ssrc[i];
            float v = __ldg(ss + s) + ddv;
            v = v > 0.f ? v : 0.2f * v;
            wgt = __expf(v - mx);
        }
        sum += wgt;
        int nn = min(32, b1 - base);
        for (int t = 0; t < nn; t++) {
            float wt = __shfl_sync(0xffffffffu, wgt, t);
            int st = __shfl_sync(0xffffffffu, s, t);
            uint4 u = __ldg((const uint4*)(H + (size_t)st * 256) + lane);
            const __half2* hh = (const __half2*)&u;
#pragma unroll
            for (int j = 0; j < 4; j++) {
                float2 f = __half22float2(hh[j]);
                acc[2 * j]     += wt * f.x;
                acc[2 * j + 1] += wt * f.y;
            }
        }
    }
#pragma unroll
    for (int o = 16; o; o >>= 1) sum += __shfl_xor_sync(0xffffffffu, sum, o);
    float inv = 1.f / (sum + 1e-16f);

    float4 bb0 = __ldg((const float4*)bias + lane * 2);
    float4 bb1 = __ldg((const float4*)bias + lane * 2 + 1);
    float4 o0, o1;
    o0.x = fmaxf(acc[0] * inv + bb0.x, 0.f); o0.y = fmaxf(acc[1] * inv + bb0.y, 0.f);
    o0.z = fmaxf(acc[2] * inv + bb0.z, 0.f); o0.w = fmaxf(acc[3] * inv + bb0.w, 0.f);
    o1.x = fmaxf(acc[4] * inv + bb1.x, 0.f); o1.y = fmaxf(acc[5] * inv + bb1.y, 0.f);
    o1.z = fmaxf(acc[6] * inv + bb1.z, 0.f); o1.w = fmaxf(acc[7] * inv + bb1.w, 0.f);

    union U4 { __half2 h2[4]; uint4 u; };
    U4 uh, ul;
    split2(o0.x, o0.y, &uh.h2[0], &ul.h2[0]);
    split2(o0.z, o0.w, &uh.h2[1], &ul.h2[1]);
    split2(o1.x, o1.y, &uh.h2[2], &ul.h2[2]);
    split2(o1.z, o1.w, &uh.h2[3], &ul.h2[3]);
    *(uint4*)(Xh + (size_t)w * 256 + lane * 8) = uh.u;
    *(uint4*)(Xl + (size_t)w * 256 + lane * 8) = ul.u;

    float4 dva = __ldg((const float4*)dvn + lane * 2);
    float4 dvb = __ldg((const float4*)dvn + lane * 2 + 1);
    float dq = o0.x * dva.x + o0.y * dva.y + o0.z * dva.z + o0.w * dva.w
             + o1.x * dvb.x + o1.y * dvb.y + o1.z * dvb.z + o1.w * dvb.w;
#pragma unroll
    for (int o = 16; o; o >>= 1) dq += __shfl_xor_sync(0xffffffffu, dq, o);
    if (lane == 0) ddn[w] = dq;
}

// ---------------- fused GAT (FOUT=16, final layer) ----------------
__global__ void __launch_bounds__(256) gat16_kernel(const int* __restrict__ rowptr,
                                                    const int* __restrict__ ssrc,
                                                    const float* __restrict__ ss,
                                                    const float* __restrict__ dd,
                                                    const float* __restrict__ H,
                                                    const float* __restrict__ bias,
                                                    float* __restrict__ out, int ndst) {
    int w = (blockIdx.x * blockDim.x + threadIdx.x) >> 5;
    int lane = threadIdx.x & 31;
    if (w >= ndst) return;
    int b0 = rowptr[w], b1 = rowptr[w + 1];
    float ddv = dd[w];
    int half = lane >> 4, fl = lane & 15;

    float mx = __int_as_float(0xff800000);
    for (int i = b0 + lane; i < b1; i += 32) {
        float v = __ldg(ss + ssrc[i]) + ddv;
        v = v > 0.f ? v : 0.2f * v;
        mx = fmaxf(mx, v);
    }
#pragma unroll
    for (int o = 16; o; o >>= 1) mx = fmaxf(mx, __shfl_xor_sync(0xffffffffu, mx, o));

    float acc = 0.f;
    float sum = 0.f;
    for (int base = b0; base < b1; base += 32) {
        int i = base + lane;
        float wgt = 0.f;
        int s = 0;
        if (i < b1) {
            s = ssrc[i];
            float v = __ldg(ss + s) + ddv;
            v = v > 0.f ? v : 0.2f * v;
            wgt = __expf(v - mx);
        }
        sum += wgt;
        int nn = min(32, b1 - base);
        for (int t = 0; t < nn; t += 2) {
            int tt = t + half;
            float wt = __shfl_sync(0xffffffffu, wgt, tt);
            int st = __shfl_sync(0xffffffffu, s, tt);
            if (tt < nn) acc += wt * __ldg(H + (size_t)st * 16 + fl);
        }
    }
#pragma unroll
    for (int o = 16; o; o >>= 1) sum += __shfl_xor_sync(0xffffffffu, sum, o);
    acc += __shfl_xor_sync(0xffffffffu, acc, 16);
    float inv = 1.f / (sum + 1e-16f);
    if (lane < 16)
        out[(size_t)w * 16 + lane] = acc * inv + __ldg(bias + lane);
}

// ---------------- readout ----------------
__global__ void sumrows16_kernel(const float* __restrict__ xb, const int* __restrict__ dstidx,
                                 float* __restrict__ out16, int L) {
    __shared__ float sh[16];
    if (threadIdx.x < 16) sh[threadIdx.x] = 0.f;
    __syncthreads();
    float loc[16];
#pragma unroll
    for (int k = 0; k < 16; k++) loc[k] = 0.f;
    for (int t = blockIdx.x * blockDim.x + threadIdx.x; t < L; t += gridDim.x * blockDim.x) {
        const float* row = xb + (size_t)dstidx[t] * 16;
#pragma unroll
        for (int k = 0; k < 16; k++) loc[k] += row[k];
    }
#pragma unroll
    for (int k = 0; k < 16; k++) atomicAdd(&sh[k], loc[k]);
    __syncthreads();
    if (threadIdx.x < 16) atomicAdd(&out16[threadIdx.x], sh[threadIdx.x]);
}

__global__ void pred_kernel(const float* __restrict__ xa, const int* __restrict__ srcidx,
                            const float* __restrict__ sum16, float* __restrict__ pred, int L) {
    int t = blockIdx.x * blockDim.x + threadIdx.x;
    if (t >= L) return;
    const float* row = xa + (size_t)srcidx[t] * 16;
    float s = 0.f;
#pragma unroll
    for (int k = 0; k < 16; k++) s += row[k] * __ldg(sum16 + k);
    pred[t] = s;
}

// ---------------- host orchestration ----------------
static inline int cdiv(int a, int b) { return (a + b - 1) / b; }

// side-stream + events, created once (resource init only; per-call work is identical)
static cudaStream_t get_side_stream() {
    static cudaStream_t s = nullptr;
    if (!s) cudaStreamCreateWithFlags(&s, cudaStreamNonBlocking);
    return s;
}
static cudaEvent_t get_event(int which) {
    static cudaEvent_t ev[2] = {nullptr, nullptr};
    if (!ev[which]) cudaEventCreateWithFlags(&ev[which], cudaEventDisableTiming);
    return ev[which];
}

extern "C" void kernel_launch(void* const* d_in, const int* in_sizes, int n_in,
                              void* d_out, int out_size) {
    const float* xAin = (const float*)d_in[0];
    const float* xBin = (const float*)d_in[1];
    const int* ei_ab = (const int*)d_in[2];
    const int* ei_ba = (const int*)d_in[3];
    const int* srcI = (const int*)d_in[4];
    const int* dstI = (const int*)d_in[5];

    const float* Wab[3]  = {(const float*)d_in[6],  (const float*)d_in[14], (const float*)d_in[22]};
    const float* asab[3] = {(const float*)d_in[7],  (const float*)d_in[15], (const float*)d_in[23]};
    const float* adab[3] = {(const float*)d_in[8],  (const float*)d_in[16], (const float*)d_in[24]};
    const float* bab[3]  = {(const float*)d_in[9],  (const float*)d_in[17], (const float*)d_in[25]};
    const float* Wba[3]  = {(const float*)d_in[10], (const float*)d_in[18], (const float*)d_in[26]};
    const float* asba[3] = {(const float*)d_in[11], (const float*)d_in[19], (const float*)d_in[27]};
    const float* adba[3] = {(const float*)d_in[12], (const float*)d_in[20], (const float*)d_in[28]};
    const float* bba[3]  = {(const float*)d_in[13], (const float*)d_in[21], (const float*)d_in[29]};

    float* out = (float*)d_out;
    float* pred = out;
    float* xaOut = out + LPRED;
    float* xbOut = xaOut + (size_t)NA * 16;

    float* F = nullptr;
    int* I = nullptr;
    cudaGetSymbolAddress((void**)&F, g_fpool);
    cudaGetSymbolAddress((void**)&I, g_ipool);

    cudaFuncSetAttribute(gemm_f16x3_kernel, cudaFuncAttributeMaxDynamicSharedMemorySize,
                         G_SMEM_TOTAL);

    __half* XAH = (__half*)(F + OFF_XAH);
    __half* XAL = (__half*)(F + OFF_XAL);
    __half* XBH = (__half*)(F + OFF_XBH);
    __half* XBL = (__half*)(F + OFF_XBL);
    float* HABf = F + OFF_HAB;
    float* HBAf = F + OFF_HBA;
    __half* HABh = (__half*)(F + OFF_HAB);
    __half* HBAh = (__half*)(F + OFF_HBA);
    float* SSAB = F + OFF_SSAB;
    float* SSBA = F + OFF_SSBA;
    float* DDAB = F + OFF_DDAB;
    float* DDBA = F + OFF_DDBA;
    float* SV = F + OFF_SV;
    float* SUM16 = F + OFF_SUM16;
    __half* WTABH = (__half*)(F + OFF_WTABH);
    __half* WTABL = (__half*)(F + OFF_WTABL);
    __half* WTBAH = (__half*)(F + OFF_WTBAH);
    __half* WTBAL = (__half*)(F + OFF_WTBAL);

    int* RP2 = I + IOFF_RP2;
    int* CNT2 = I + IOFF_CNT2;
    int* FILL2 = I + IOFF_FILL2;
    int* SRT = I + IOFF_SRT;
    int* BSUM = I + IOFF_BSUM;

    const int FinL[3] = {128, 256, 256};
    const int FoutL[3] = {256, 256, 16};

    cudaStream_t s1 = get_side_stream();
    cudaEvent_t evFork = get_event(0);
    cudaEvent_t evCsr = get_event(1);

    // ---- fork: CSR build on side stream (independent of layer-1 prologue) ----
    cudaEventRecord(evFork, 0);
    cudaStreamWaitEvent(s1, evFork, 0);

    const int NSEG = NA + NB;
    const int nScanBlk = cdiv(NSEG, 1024);
    cudaMemsetAsync(CNT2, 0, NSEG * sizeof(int), s1);
    hist2_kernel<<<cdiv(2 * NEDGE, 256), 256, 0, s1>>>(ei_ab, ei_ba, CNT2);
    scan1_kernel<<<nScanBlk, 1024, 0, s1>>>(CNT2, RP2, BSUM, NSEG);
    scan2_kernel<<<1, 128, 0, s1>>>(BSUM, nScanBlk);
    scan3_kernel<<<nScanBlk, 1024, 0, s1>>>(RP2, BSUM, NSEG);
    cudaMemsetAsync(FILL2, 0, NSEG * sizeof(int), s1);
    scatter2_kernel<<<cdiv(2 * NEDGE, 256), 256, 0, s1>>>(ei_ab, ei_ba, RP2, FILL2, SRT);
    cudaEventRecord(evCsr, s1);

    // ---- main stream: dv projections + layer-1 prologue (overlaps CSR) ----
    for (int l = 0; l < 3; l++)
        wv2_kernel<<<dim3(cdiv(FinL[l], 8), 2), 256>>>(
            Wab[l], adab[l], SV + l * 512, Wba[l], adba[l], SV + l * 512 + 256,
            FinL[l], FoutL[l]);

    splitX_kernel<<<cdiv(NA, 8), 256>>>(xAin, XAH, XAL, SV + 256, DDBA, NA);
    splitX_kernel<<<cdiv(NB, 8), 256>>>(xBin, XBH, XBL, SV + 0, DDAB, NB);

    bool joined = false;
    for (int l = 0; l < 3; l++) {
        int Fin = FinL[l];

        if (l < 2) {
            cudaMemsetAsync(SSAB, 0, 2 * NA * sizeof(float), 0);  // SSAB + SSBA
            transpose2split_kernel<<<dim3(256 / 32, Fin / 32, 2), dim3(32, 8)>>>(
                Wab[l], WTABH, WTABL, Wba[l], WTBAH, WTBAL, Fin, 256);
            gemm_f16x3_kernel<<<dim3(cdiv(NA, 128), 2), 256, G_SMEM_TOTAL>>>(
                XAH, XAL, WTABH, WTABL, HABh, NA, 256, Fin, asab[l], SSAB);
            gemm_f16x3_kernel<<<dim3(cdiv(NB, 128), 2), 256, G_SMEM_TOTAL>>>(
                XBH, XBL, WTBAH, WTBAL, HBAh, NB, 256, Fin, asba[l], SSBA);

            if (!joined) {                 // join CSR stream before first gat use
                cudaStreamWaitEvent(0, evCsr, 0);
                joined = true;
            }
            gat256h_kernel<<<cdiv(NB, 8), 256>>>(RP2, SRT, SSAB, DDAB, HABh, bab[l],
                                                 XBH, XBL, SV + (l + 1) * 512, DDAB, NB);
            gat256h_kernel<<<cdiv(NA, 8), 256>>>(RP2 + NB, SRT, SSBA, DDBA, HBAh, bba[l],
                                                 XAH, XAL, SV + (l + 1) * 512 + 256, DDBA, NA);
        } else {
            gemm_n16_kernel<<<cdiv(NA, 32), 512>>>(XAH, XAL, Wab[l], HABf, NA, asab[l], SSAB);
            gemm_n16_kernel<<<cdiv(NB, 32), 512>>>(XBH, XBL, Wba[l], HBAf, NB, asba[l], SSBA);

            gat16_kernel<<<cdiv(NB, 8), 256>>>(RP2, SRT, SSAB, DDAB, HABf, bab[l], xbOut, NB);
            gat16_kernel<<<cdiv(NA, 8), 256>>>(RP2 + NB, SRT, SSBA, DDBA, HBAf, bba[l], xaOut, NA);
        }
    }

    // ---- readout ----
    cudaMemsetAsync(SUM16, 0, 16 * sizeof(float), 0);
    sumrows16_kernel<<<256, 256>>>(xbOut, dstI, SUM16, LPRED);
    pred_kernel<<<cdiv(LPRED, 256), 256>>>(xaOut, srcI, SUM16, pred, LPRED);
}

// round 14
// speedup vs baseline: 1.1784x; 1.0270x over previous
#include <cuda_runtime.h>
#include <cuda_fp16.h>
#include <math.h>
#include <stdint.h>

#define NA 50000
#define NB 50000
#define NEDGE 1000000
#define LPRED 100000

// ---------------- device scratch pools ----------------
#define OFF_XAH   0u
#define OFF_XAL   6400000u
#define OFF_XBH   12800000u
#define OFF_XBL   19200000u
#define OFF_HAB   25600000u
#define OFF_HBA   38400000u
#define OFF_SSAB  51200000u
#define OFF_SSBA  51250000u
#define OFF_DDAB  51300000u
#define OFF_DDBA  51350000u
#define OFF_SV    51400000u             // 6*256 dv vectors (padded 2048)
#define OFF_SUM16 51402048u
#define OFF_WTABH 51402064u
#define OFF_WTABL 51434832u
#define OFF_WTBAH 51467600u
#define OFF_WTBAL 51500368u
#define FPOOL_N   51533136u

#define IOFF_RP2   0u
#define IOFF_CNT2  100001u
#define IOFF_FILL2 200001u
#define IOFF_SRT   300001u
#define IOFF_BSUM  2300001u
#define IPOOL_N    2300129u

static __device__ float g_fpool[FPOOL_N];
static __device__ int   g_ipool[IPOOL_N];

// ---------------- fp16 hi/lo split helpers ----------------
__device__ __forceinline__ void split2(float x, float y, __half2* ph, __half2* pl) {
    float hx = __uint_as_float(__float_as_uint(x) & 0xFFFFE000u);
    float hy = __uint_as_float(__float_as_uint(y) & 0xFFFFE000u);
    *ph = __halves2half2(__float2half_rn(hx), __float2half_rn(hy));
    *pl = __halves2half2(__float2half_rn(x - hx), __float2half_rn(y - hy));
}

__device__ __forceinline__ void split_store4(float4 v, __half* ph, __half* pl) {
    __half2 h01, l01, h23, l23;
    split2(v.x, v.y, &h01, &l01);
    split2(v.z, v.w, &h23, &l23);
    *(__half2*)(ph)     = h01;
    *(__half2*)(ph + 2) = h23;
    *(__half2*)(pl)     = l01;
    *(__half2*)(pl + 2) = l23;
}

#define MMA_F16(cc, aa, bb)                                                         \
    asm volatile(                                                                   \
        "mma.sync.aligned.m16n8k16.row.col.f32.f16.f16.f32 "                        \
        "{%0,%1,%2,%3},{%4,%5,%6,%7},{%8,%9},{%0,%1,%2,%3};\n"                      \
        : "+f"((cc)[0]), "+f"((cc)[1]), "+f"((cc)[2]), "+f"((cc)[3])                \
        : "r"((aa)[0]), "r"((aa)[1]), "r"((aa)[2]), "r"((aa)[3]),                   \
          "r"((bb)[0]), "r"((bb)[1]))

// dynamic smem layout for the GEMM (K-tile 64, rows padded to 72 halves = 144B)
#define GA_H 0
#define GA_L 18432
#define GB_H 36864
#define GB_L 55296
#define G_SSRED 73728
#define G_SMEM_TOTAL 74240
#define ROWP 72

// ---------------- HMMA GEMM, K-tile 64, pre-split operands ----------------
__global__ void __launch_bounds__(256) gemm_f16x3_kernel(const __half* __restrict__ Ahg,
                                                         const __half* __restrict__ Alg,
                                                         const __half* __restrict__ Bhg,
                                                         const __half* __restrict__ Blg,
                                                         __half* __restrict__ C,
                                                         int M, int N, int K,
                                                         const float* __restrict__ sv,
                                                         float* __restrict__ ssOut) {
    extern __shared__ char smc[];
    __half* Ah = (__half*)(smc + GA_H);
    __half* Al = (__half*)(smc + GA_L);
    __half* Bh = (__half*)(smc + GB_H);
    __half* Bl = (__half*)(smc + GB_L);
    float* ssred = (float*)(smc + G_SSRED);

    int tid = threadIdx.x;
    int warp = tid >> 5, lane = tid & 31;
    int g = lane >> 2, tg = lane & 3;
    int wm = warp >> 2, wn = warp & 3;
    int bm = blockIdx.x * 128, bn = blockIdx.y * 128;

    float c[4][4][4] = {};

    for (int k0 = 0; k0 < K; k0 += 64) {
#pragma unroll
        for (int j = 0; j < 4; j++) {
            int idx = tid + j * 256;
            int row = idx >> 3, q = idx & 7;
            uint4 vh = make_uint4(0, 0, 0, 0), vl = make_uint4(0, 0, 0, 0);
            int gr = bm + row;
            if (gr < M) {
                vh = *(const uint4*)(Ahg + (size_t)gr * K + k0 + q * 8);
                vl = *(const uint4*)(Alg + (size_t)gr * K + k0 + q * 8);
            }
            *(uint4*)&Ah[row * ROWP + q * 8] = vh;
            *(uint4*)&Al[row * ROWP + q * 8] = vl;
            uint4 wh = *(const uint4*)(Bhg + (size_t)(bn + row) * K + k0 + q * 8);
            uint4 wl = *(const uint4*)(Blg + (size_t)(bn + row) * K + k0 + q * 8);
            *(uint4*)&Bh[row * ROWP + q * 8] = wh;
            *(uint4*)&Bl[row * ROWP + q * 8] = wl;
        }
        __syncthreads();

#pragma unroll
        for (int ks = 0; ks < 4; ks++) {
            int kc = ks * 16 + tg * 2;
            unsigned ah[4][4], al[4][4], bh[4][2], bl[4][2];
#pragma unroll
            for (int mt = 0; mt < 4; mt++) {
                int r = wm * 64 + mt * 16 + g;
                ah[mt][0] = *(const unsigned*)&Ah[r * ROWP + kc];
                ah[mt][1] = *(const unsigned*)&Ah[(r + 8) * ROWP + kc];
                ah[mt][2] = *(const unsigned*)&Ah[r * ROWP + kc + 8];
                ah[mt][3] = *(const unsigned*)&Ah[(r + 8) * ROWP + kc + 8];
                al[mt][0] = *(const unsigned*)&Al[r * ROWP + kc];
                al[mt][1] = *(const unsigned*)&Al[(r + 8) * ROWP + kc];
                al[mt][2] = *(const unsigned*)&Al[r * ROWP + kc + 8];
                al[mt][3] = *(const unsigned*)&Al[(r + 8) * ROWP + kc + 8];
            }
#pragma unroll
            for (int nt = 0; nt < 4; nt++) {
                int n = wn * 32 + nt * 8 + g;
                bh[nt][0] = *(const unsigned*)&Bh[n * ROWP + kc];
                bh[nt][1] = *(const unsigned*)&Bh[n * ROWP + kc + 8];
                bl[nt][0] = *(const unsigned*)&Bl[n * ROWP + kc];
                bl[nt][1] = *(const unsigned*)&Bl[n * ROWP + kc + 8];
            }
#pragma unroll
            for (int mt = 0; mt < 4; mt++)
#pragma unroll
                for (int nt = 0; nt < 4; nt++) {
                    MMA_F16(c[mt][nt], ah[mt], bl[nt]);
                    MMA_F16(c[mt][nt], al[mt], bh[nt]);
                    MMA_F16(c[mt][nt], ah[mt], bh[nt]);
                }
        }
        __syncthreads();
    }

    if (tid < 128) ssred[tid] = 0.f;
    __syncthreads();
#pragma unroll
    for (int mt = 0; mt < 4; mt++) {
        float p0 = 0.f, p1 = 0.f;
#pragma unroll
        for (int nt = 0; nt < 4; nt++) {
            int col0 = bn + wn * 32 + nt * 8 + tg * 2;
            float2 sva = __ldg((const float2*)sv + (col0 >> 1));
            p0 += c[mt][nt][0] * sva.x + c[mt][nt][1] * sva.y;
            p1 += c[mt][nt][2] * sva.x + c[mt][nt][3] * sva.y;
        }
        p0 += __shfl_xor_sync(0xffffffffu, p0, 1);
        p0 += __shfl_xor_sync(0xffffffffu, p0, 2);
        p1 += __shfl_xor_sync(0xffffffffu, p1, 1);
        p1 += __shfl_xor_sync(0xffffffffu, p1, 2);
        if (tg == 0) {
            int rl = wm * 64 + mt * 16 + g;
            atomicAdd(&ssred[rl], p0);
            atomicAdd(&ssred[rl + 8], p1);
        }
    }
    __syncthreads();
    if (tid < 128) {
        int row = bm + tid;
        if (row < M) atomicAdd(ssOut + row, ssred[tid]);
    }

#pragma unroll
    for (int mt = 0; mt < 4; mt++) {
        int r0 = bm + wm * 64 + mt * 16 + g;
#pragma unroll
        for (int nt = 0; nt < 4; nt++) {
            int cc = bn + wn * 32 + nt * 8 + tg * 2;
            __half2 p0 = __floats2half2_rn(c[mt][nt][0], c[mt][nt][1]);
            __half2 p1 = __floats2half2_rn(c[mt][nt][2], c[mt][nt][3]);
            if (r0 < M)     *(__half2*)(C + (size_t)r0 * N + cc) = p0;
            if (r0 + 8 < M) *(__half2*)(C + (size_t)(r0 + 8) * N + cc) = p1;
        }
    }
}

// ---------------- transpose + split weights ----------------
__global__ void transpose2split_kernel(const float* __restrict__ W0,
                                       __half* __restrict__ T0h, __half* __restrict__ T0l,
                                       const float* __restrict__ W1,
                                       __half* __restrict__ T1h, __half* __restrict__ T1l,
                                       int K, int N) {
    __shared__ float t[32][33];
    const float* W = blockIdx.z ? W1 : W0;
    __half* Th = blockIdx.z ? T1h : T0h;
    __half* Tl = blockIdx.z ? T1l : T0l;
    int n0 = blockIdx.x * 32, k0 = blockIdx.y * 32;
#pragma unroll
    for (int i = 0; i < 4; i++) {
        int k = k0 + threadIdx.y + i * 8;
        t[threadIdx.y + i * 8][threadIdx.x] = W[(size_t)k * N + n0 + threadIdx.x];
    }
    __syncthreads();
#pragma unroll
    for (int i = 0; i < 4; i++) {
        int n = n0 + threadIdx.y + i * 8;
        float v = t[threadIdx.x][threadIdx.y + i * 8];
        float hv = __uint_as_float(__float_as_uint(v) & 0xFFFFE000u);
        Th[(size_t)n * K + k0 + threadIdx.x] = __float2half_rn(hv);
        Tl[(size_t)n * K + k0 + threadIdx.x] = __float2half_rn(v - hv);
    }
}

// ---------------- layer-1 X split (K=128) + dd dot ----------------
__global__ void splitX_kernel(const float* __restrict__ X,
                              __half* __restrict__ Xh, __half* __restrict__ Xl,
                              const float* __restrict__ dv, float* __restrict__ dd,
                              int M) {
    int w = (blockIdx.x * blockDim.x + threadIdx.x) >> 5;
    int lane = threadIdx.x & 31;
    if (w >= M) return;
    float4 v = *(const float4*)(X + (size_t)w * 128 + lane * 4);
    float4 dvv = __ldg((const float4*)dv + lane);
    float acc = v.x * dvv.x + v.y * dvv.y + v.z * dvv.z + v.w * dvv.w;
    split_store4(v, Xh + (size_t)w * 128 + lane * 4, Xl + (size_t)w * 128 + lane * 4);
#pragma unroll
    for (int o = 16; o; o >>= 1) acc += __shfl_xor_sync(0xffffffffu, acc, o);
    if (lane == 0) dd[w] = acc;
}

// ---------------- small-N GEMM (layer 3) ----------------
__global__ void __launch_bounds__(512) gemm_n16_kernel(const __half* __restrict__ Xh,
                                                       const __half* __restrict__ Xl,
                                                       const float* __restrict__ W,
                                                       float* __restrict__ H, int M,
                                                       const float* __restrict__ sv,
                                                       float* __restrict__ ssOut) {
    __shared__ float Ws[256 * 16];
    __shared__ float Xs[32 * 256];
    int tid = threadIdx.x;
    int row0 = blockIdx.x * 32;
    for (int i = tid; i < 256 * 16 / 4; i += 512)
        *(float4*)&Ws[i * 4] = *(const float4*)(W + i * 4);
#pragma unroll
    for (int i = 0; i < 4; i++) {
        int lin = tid + i * 512;
        int r = lin / 64;
        int c4 = lin % 64;
        float4 v = make_float4(0.f, 0.f, 0.f, 0.f);
        if (row0 + r < M) {
            uint2 vh = *(const uint2*)(Xh + (size_t)(row0 + r) * 256 + c4 * 4);
            uint2 vl = *(const uint2*)(Xl + (size_t)(row0 + r) * 256 + c4 * 4);
            const __half2* ph = (const __half2*)&vh;
            const __half2* pl = (const __half2*)&vl;
            float2 a0 = __half22float2(ph[0]), a1 = __half22float2(ph[1]);
            float2 b0 = __half22float2(pl[0]), b1 = __half22float2(pl[1]);
            v = make_float4(a0.x + b0.x, a0.y + b0.y, a1.x + b1.x, a1.y + b1.y);
        }
        *(float4*)&Xs[r * 256 + c4 * 4] = v;
    }
    __syncthreads();

    int r = tid / 16, c = tid % 16;
    float acc = 0.f;
#pragma unroll 8
    for (int k = 0; k < 256; k++) acc += Xs[r * 256 + k] * Ws[k * 16 + c];

    float sp = acc * __ldg(sv + c);
    sp += __shfl_xor_sync(0xffffffffu, sp, 1);
    sp += __shfl_xor_sync(0xffffffffu, sp, 2);
    sp += __shfl_xor_sync(0xffffffffu, sp, 4);
    sp += __shfl_xor_sync(0xffffffffu, sp, 8);
    if (row0 + r < M) {
        if ((tid & 15) == 0) ssOut[row0 + r] = sp;
        H[(size_t)(row0 + r) * 16 + c] = acc;
    }
}

// ---------------- fused dual W@a ----------------
__global__ void wv2_kernel(const float* __restrict__ W0, const float* __restrict__ a0,
                           float* __restrict__ o0,
                           const float* __restrict__ W1, const float* __restrict__ a1,
                           float* __restrict__ o1, int Fin, int Fout) {
    const float* W = blockIdx.y ? W1 : W0;
    const float* a = blockIdx.y ? a1 : a0;
    float* o = blockIdx.y ? o1 : o0;
    int w = (blockIdx.x * blockDim.x + threadIdx.x) >> 5;
    int lane = threadIdx.x & 31;
    if (w >= Fin) return;
    float s = 0.f;
    for (int j = lane; j < Fout; j += 32) s += W[(size_t)w * Fout + j] * a[j];
    for (int o2 = 16; o2; o2 >>= 1) s += __shfl_down_sync(0xffffffffu, s, o2);
    if (lane == 0) o[w] = s;
}

// ---------------- concatenated 2-direction CSR build ----------------
__global__ void hist2_kernel(const int* __restrict__ eab, const int* __restrict__ eba,
                             int* __restrict__ cnt) {
    int e = blockIdx.x * blockDim.x + threadIdx.x;
    if (e < NEDGE) atomicAdd(&cnt[eab[NEDGE + e]], 1);
    else if (e < 2 * NEDGE) atomicAdd(&cnt[NB + eba[NEDGE + e - NEDGE]], 1);
}

__global__ void scan1_kernel(const int* __restrict__ cnt, int* __restrict__ rowptr,
                             int* __restrict__ bsum, int n) {
    __shared__ int sh[1024];
    int i = blockIdx.x * 1024 + threadIdx.x;
    int v = (i < n) ? cnt[i] : 0;
    sh[threadIdx.x] = v;
    __syncthreads();
    for (int off = 1; off < 1024; off <<= 1) {
        int t = (threadIdx.x >= off) ? sh[threadIdx.x - off] : 0;
        __syncthreads();
        sh[threadIdx.x] += t;
        __syncthreads();
    }
    if (i < n) rowptr[i + 1] = sh[threadIdx.x];
    if (threadIdx.x == 1023) bsum[blockIdx.x] = sh[1023];
}

__global__ void scan2_kernel(int* __restrict__ bsum, int nb) {
    __shared__ int sh[128];
    int t = threadIdx.x;
    int v = (t < nb) ? bsum[t] : 0;
    sh[t] = v;
    __syncthreads();
    for (int off = 1; off < 128; off <<= 1) {
        int u = (t >= off) ? sh[t - off] : 0;
        __syncthreads();
        sh[t] += u;
        __syncthreads();
    }
    if (t < nb) bsum[t] = sh[t] - v;
}

__global__ void scan3_kernel(int* __restrict__ rowptr, const int* __restrict__ bsum, int n) {
    int i = blockIdx.x * 1024 + threadIdx.x;
    if (i < n) rowptr[i + 1] += bsum[blockIdx.x];
    if (i == 0) rowptr[0] = 0;
}

__global__ void scatter2_kernel(const int* __restrict__ eab, const int* __restrict__ eba,
                                const int* __restrict__ rowptr, int* __restrict__ fill,
                                int* __restrict__ sorted) {
    int e = blockIdx.x * blockDim.x + threadIdx.x;
    int s, seg;
    if (e < NEDGE) { s = eab[e]; seg = eab[NEDGE + e]; }
    else if (e < 2 * NEDGE) { int e2 = e - NEDGE; s = eba[e2]; seg = NB + eba[NEDGE + e2]; }
    else return;
    int p = rowptr[seg] + atomicAdd(&fill[seg], 1);
    sorted[p] = s;
}

// ---------------- fused GAT (FOUT=256): cached-logit, fp16 gather ----------------
__global__ void __launch_bounds__(256) gat256h_kernel(const int* __restrict__ rowptr,
                                                      const int* __restrict__ ssrc,
                                                      const float* __restrict__ ss,
                                                      const float* __restrict__ dd,
                                                      const __half* __restrict__ H,
                                                      const float* __restrict__ bias,
                                                      __half* __restrict__ Xh,
                                                      __half* __restrict__ Xl,
                                                      const float* __restrict__ dvn,
                                                      float* __restrict__ ddn,
                                                      int ndst) {
    int w = (blockIdx.x * blockDim.x + threadIdx.x) >> 5;
    int lane = threadIdx.x & 31;
    if (w >= ndst) return;
    int b0 = rowptr[w], b1 = rowptr[w + 1];
    float ddv = dd[w];

    // pass 1: segment max; cache first-iteration logit per lane (covers deg<=32, ~99.5%)
    float cv = 0.f;
    float mx = __int_as_float(0xff800000);
    {
        int i = b0 + lane;
        if (i < b1) {
            float v = __ldg(ss + ssrc[i]) + ddv;
            v = v > 0.f ? v : 0.2f * v;
            cv = v;
            mx = v;
        }
        for (i += 32; i < b1; i += 32) {
            float v = __ldg(ss + ssrc[i]) + ddv;
            v = v > 0.f ? v : 0.2f * v;
            mx = fmaxf(mx, v);
        }
    }
#pragma unroll
    for (int o = 16; o; o >>= 1) mx = fmaxf(mx, __shfl_xor_sync(0xffffffffu, mx, o));

    float acc[8] = {};
    float sum = 0.f;
    for (int base = b0; base < b1; base += 32) {
        int i = base + lane;
        float wgt = 0.f;
        int s = 0;
        if (i < b1) {
            s = ssrc[i];
            float v;
            if (base == b0) {
                v = cv;                      // reuse cached logit (skip ss gather)
            } else {
                v = __ldg(ss + s) + ddv;
                v = v > 0.f ? v : 0.2f * v;
            }
            wgt = __expf(v - mx);
        }
        sum += wgt;
        int nn = min(32, b1 - base);
        for (int t = 0; t < nn; t++) {
            float wt = __shfl_sync(0xffffffffu, wgt, t);
            int st = __shfl_sync(0xffffffffu, s, t);
            uint4 u = __ldg((const uint4*)(H + (size_t)st * 256) + lane);
            const __half2* hh = (const __half2*)&u;
#pragma unroll
            for (int j = 0; j < 4; j++) {
                float2 f = __half22float2(hh[j]);
                acc[2 * j]     += wt * f.x;
                acc[2 * j + 1] += wt * f.y;
            }
        }
    }
#pragma unroll
    for (int o = 16; o; o >>= 1) sum += __shfl_xor_sync(0xffffffffu, sum, o);
    float inv = 1.f / (sum + 1e-16f);

    float4 bb0 = __ldg((const float4*)bias + lane * 2);
    float4 bb1 = __ldg((const float4*)bias + lane * 2 + 1);
    float4 o0, o1;
    o0.x = fmaxf(acc[0] * inv + bb0.x, 0.f); o0.y = fmaxf(acc[1] * inv + bb0.y, 0.f);
    o0.z = fmaxf(acc[2] * inv + bb0.z, 0.f); o0.w = fmaxf(acc[3] * inv + bb0.w, 0.f);
    o1.x = fmaxf(acc[4] * inv + bb1.x, 0.f); o1.y = fmaxf(acc[5] * inv + bb1.y, 0.f);
    o1.z = fmaxf(acc[6] * inv + bb1.z, 0.f); o1.w = fmaxf(acc[7] * inv + bb1.w, 0.f);

    union U4 { __half2 h2[4]; uint4 u; };
    U4 uh, ul;
    split2(o0.x, o0.y, &uh.h2[0], &ul.h2[0]);
    split2(o0.z, o0.w, &uh.h2[1], &ul.h2[1]);
    split2(o1.x, o1.y, &uh.h2[2], &ul.h2[2]);
    split2(o1.z, o1.w, &uh.h2[3], &ul.h2[3]);
    *(uint4*)(Xh + (size_t)w * 256 + lane * 8) = uh.u;
    *(uint4*)(Xl + (size_t)w * 256 + lane * 8) = ul.u;

    float4 dva = __ldg((const float4*)dvn + lane * 2);
    float4 dvb = __ldg((const float4*)dvn + lane * 2 + 1);
    float dq = o0.x * dva.x + o0.y * dva.y + o0.z * dva.z + o0.w * dva.w
             + o1.x * dvb.x + o1.y * dvb.y + o1.z * dvb.z + o1.w * dvb.w;
#pragma unroll
    for (int o = 16; o; o >>= 1) dq += __shfl_xor_sync(0xffffffffu, dq, o);
    if (lane == 0) ddn[w] = dq;
}

// ---------------- fused GAT (FOUT=16, final layer): cached-logit ----------------
__global__ void __launch_bounds__(256) gat16_kernel(const int* __restrict__ rowptr,
                                                    const int* __restrict__ ssrc,
                                                    const float* __restrict__ ss,
                                                    const float* __restrict__ dd,
                                                    const float* __restrict__ H,
                                                    const float* __restrict__ bias,
                                                    float* __restrict__ out, int ndst) {
    int w = (blockIdx.x * blockDim.x + threadIdx.x) >> 5;
    int lane = threadIdx.x & 31;
    if (w >= ndst) return;
    int b0 = rowptr[w], b1 = rowptr[w + 1];
    float ddv = dd[w];
    int half = lane >> 4, fl = lane & 15;

    float cv = 0.f;
    float mx = __int_as_float(0xff800000);
    {
        int i = b0 + lane;
        if (i < b1) {
            float v = __ldg(ss + ssrc[i]) + ddv;
            v = v > 0.f ? v : 0.2f * v;
            cv = v;
            mx = v;
        }
        for (i += 32; i < b1; i += 32) {
            float v = __ldg(ss + ssrc[i]) + ddv;
            v = v > 0.f ? v : 0.2f * v;
            mx = fmaxf(mx, v);
        }
    }
#pragma unroll
    for (int o = 16; o; o >>= 1) mx = fmaxf(mx, __shfl_xor_sync(0xffffffffu, mx, o));

    float acc = 0.f;
    float sum = 0.f;
    for (int base = b0; base < b1; base += 32) {
        int i = base + lane;
        float wgt = 0.f;
        int s = 0;
        if (i < b1) {
            s = ssrc[i];
            float v;
            if (base == b0) {
                v = cv;
            } else {
                v = __ldg(ss + s) + ddv;
                v = v > 0.f ? v : 0.2f * v;
            }
            wgt = __expf(v - mx);
        }
        sum += wgt;
        int nn = min(32, b1 - base);
        for (int t = 0; t < nn; t += 2) {
            int tt = t + half;
            float wt = __shfl_sync(0xffffffffu, wgt, tt);
            int st = __shfl_sync(0xffffffffu, s, tt);
            if (tt < nn) acc += wt * __ldg(H + (size_t)st * 16 + fl);
        }
    }
#pragma unroll
    for (int o = 16; o; o >>= 1) sum += __shfl_xor_sync(0xffffffffu, sum, o);
    acc += __shfl_xor_sync(0xffffffffu, acc, 16);
    float inv = 1.f / (sum + 1e-16f);
    if (lane < 16)
        out[(size_t)w * 16 + lane] = acc * inv + __ldg(bias + lane);
}

// ---------------- readout ----------------
__global__ void sumrows16_kernel(const float* __restrict__ xb, const int* __restrict__ dstidx,
                                 float* __restrict__ out16, int L) {
    __shared__ float sh[16];
    if (threadIdx.x < 16) sh[threadIdx.x] = 0.f;
    __syncthreads();
    float loc[16];
#pragma unroll
    for (int k = 0; k < 16; k++) loc[k] = 0.f;
    for (int t = blockIdx.x * blockDim.x + threadIdx.x; t < L; t += gridDim.x * blockDim.x) {
        const float* row = xb + (size_t)dstidx[t] * 16;
#pragma unroll
        for (int k = 0; k < 16; k++) loc[k] += row[k];
    }
#pragma unroll
    for (int k = 0; k < 16; k++) atomicAdd(&sh[k], loc[k]);
    __syncthreads();
    if (threadIdx.x < 16) atomicAdd(&out16[threadIdx.x], sh[threadIdx.x]);
}

__global__ void pred_kernel(const float* __restrict__ xa, const int* __restrict__ srcidx,
                            const float* __restrict__ sum16, float* __restrict__ pred, int L) {
    int t = blockIdx.x * blockDim.x + threadIdx.x;
    if (t >= L) return;
    const float* row = xa + (size_t)srcidx[t] * 16;
    float s = 0.f;
#pragma unroll
    for (int k = 0; k < 16; k++) s += row[k] * __ldg(sum16 + k);
    pred[t] = s;
}

// ---------------- host orchestration ----------------
static inline int cdiv(int a, int b) { return (a + b - 1) / b; }

static cudaStream_t get_side_stream() {
    static cudaStream_t s = nullptr;
    if (!s) cudaStreamCreateWithFlags(&s, cudaStreamNonBlocking);
    return s;
}
static cudaEvent_t get_event(int which) {
    static cudaEvent_t ev[4] = {nullptr, nullptr, nullptr, nullptr};
    if (!ev[which]) cudaEventCreateWithFlags(&ev[which], cudaEventDisableTiming);
    return ev[which];
}

extern "C" void kernel_launch(void* const* d_in, const int* in_sizes, int n_in,
                              void* d_out, int out_size) {
    const float* xAin = (const float*)d_in[0];
    const float* xBin = (const float*)d_in[1];
    const int* ei_ab = (const int*)d_in[2];
    const int* ei_ba = (const int*)d_in[3];
    const int* srcI = (const int*)d_in[4];
    const int* dstI = (const int*)d_in[5];

    const float* Wab[3]  = {(const float*)d_in[6],  (const float*)d_in[14], (const float*)d_in[22]};
    const float* asab[3] = {(const float*)d_in[7],  (const float*)d_in[15], (const float*)d_in[23]};
    const float* adab[3] = {(const float*)d_in[8],  (const float*)d_in[16], (const float*)d_in[24]};
    const float* bab[3]  = {(const float*)d_in[9],  (const float*)d_in[17], (const float*)d_in[25]};
    const float* Wba[3]  = {(const float*)d_in[10], (const float*)d_in[18], (const float*)d_in[26]};
    const float* asba[3] = {(const float*)d_in[11], (const float*)d_in[19], (const float*)d_in[27]};
    const float* adba[3] = {(const float*)d_in[12], (const float*)d_in[20], (const float*)d_in[28]};
    const float* bba[3]  = {(const float*)d_in[13], (const float*)d_in[21], (const float*)d_in[29]};

    float* out = (float*)d_out;
    float* pred = out;
    float* xaOut = out + LPRED;
    float* xbOut = xaOut + (size_t)NA * 16;

    float* F = nullptr;
    int* I = nullptr;
    cudaGetSymbolAddress((void**)&F, g_fpool);
    cudaGetSymbolAddress((void**)&I, g_ipool);

    cudaFuncSetAttribute(gemm_f16x3_kernel, cudaFuncAttributeMaxDynamicSharedMemorySize,
                         G_SMEM_TOTAL);

    __half* XAH = (__half*)(F + OFF_XAH);
    __half* XAL = (__half*)(F + OFF_XAL);
    __half* XBH = (__half*)(F + OFF_XBH);
    __half* XBL = (__half*)(F + OFF_XBL);
    float* HABf = F + OFF_HAB;
    float* HBAf = F + OFF_HBA;
    __half* HABh = (__half*)(F + OFF_HAB);
    __half* HBAh = (__half*)(F + OFF_HBA);
    float* SSAB = F + OFF_SSAB;
    float* SSBA = F + OFF_SSBA;
    float* DDAB = F + OFF_DDAB;
    float* DDBA = F + OFF_DDBA;
    float* SV = F + OFF_SV;
    float* SUM16 = F + OFF_SUM16;
    __half* WTABH = (__half*)(F + OFF_WTABH);
    __half* WTABL = (__half*)(F + OFF_WTABL);
    __half* WTBAH = (__half*)(F + OFF_WTBAH);
    __half* WTBAL = (__half*)(F + OFF_WTBAL);

    int* RP2 = I + IOFF_RP2;
    int* CNT2 = I + IOFF_CNT2;
    int* FILL2 = I + IOFF_FILL2;
    int* SRT = I + IOFF_SRT;
    int* BSUM = I + IOFF_BSUM;

    const int FinL[3] = {128, 256, 256};
    const int FoutL[3] = {256, 256, 16};

    cudaStream_t s1 = get_side_stream();
    cudaEvent_t evFork = get_event(0);
    cudaEvent_t evCsr = get_event(1);
    cudaEvent_t evFork3 = get_event(2);
    cudaEvent_t evL3 = get_event(3);

    // ---- fork: CSR build on side stream ----
    cudaEventRecord(evFork, 0);
    cudaStreamWaitEvent(s1, evFork, 0);

    const int NSEG = NA + NB;
    const int nScanBlk = cdiv(NSEG, 1024);
    cudaMemsetAsync(CNT2, 0, NSEG * sizeof(int), s1);
    hist2_kernel<<<cdiv(2 * NEDGE, 256), 256, 0, s1>>>(ei_ab, ei_ba, CNT2);
    scan1_kernel<<<nScanBlk, 1024, 0, s1>>>(CNT2, RP2, BSUM, NSEG);
    scan2_kernel<<<1, 128, 0, s1>>>(BSUM, nScanBlk);
    scan3_kernel<<<nScanBlk, 1024, 0, s1>>>(RP2, BSUM, NSEG);
    cudaMemsetAsync(FILL2, 0, NSEG * sizeof(int), s1);
    scatter2_kernel<<<cdiv(2 * NEDGE, 256), 256, 0, s1>>>(ei_ab, ei_ba, RP2, FILL2, SRT);
    cudaEventRecord(evCsr, s1);

    // ---- main stream: dv projections + layer-1 prologue ----
    for (int l = 0; l < 3; l++)
        wv2_kernel<<<dim3(cdiv(FinL[l], 8), 2), 256>>>(
            Wab[l], adab[l], SV + l * 512, Wba[l], adba[l], SV + l * 512 + 256,
            FinL[l], FoutL[l]);

    splitX_kernel<<<cdiv(NA, 8), 256>>>(xAin, XAH, XAL, SV + 256, DDBA, NA);
    splitX_kernel<<<cdiv(NB, 8), 256>>>(xBin, XBH, XBL, SV + 0, DDAB, NB);

    // ---- layers 1-2 (sequential, R12 structure) ----
    bool joined = false;
    for (int l = 0; l < 2; l++) {
        int Fin = FinL[l];
        cudaMemsetAsync(SSAB, 0, 2 * NA * sizeof(float), 0);
        transpose2split_kernel<<<dim3(256 / 32, Fin / 32, 2), dim3(32, 8)>>>(
            Wab[l], WTABH, WTABL, Wba[l], WTBAH, WTBAL, Fin, 256);
        gemm_f16x3_kernel<<<dim3(cdiv(NA, 128), 2), 256, G_SMEM_TOTAL>>>(
            XAH, XAL, WTABH, WTABL, HABh, NA, 256, Fin, asab[l], SSAB);
        gemm_f16x3_kernel<<<dim3(cdiv(NB, 128), 2), 256, G_SMEM_TOTAL>>>(
            XBH, XBL, WTBAH, WTBAL, HBAh, NB, 256, Fin, asba[l], SSBA);

        if (!joined) {
            cudaStreamWaitEvent(0, evCsr, 0);
            joined = true;
        }
        gat256h_kernel<<<cdiv(NB, 8), 256>>>(RP2, SRT, SSAB, DDAB, HABh, bab[l],
                                             XBH, XBL, SV + (l + 1) * 512, DDAB, NB);
        gat256h_kernel<<<cdiv(NA, 8), 256>>>(RP2 + NB, SRT, SSBA, DDBA, HBAh, bba[l],
                                             XAH, XAL, SV + (l + 1) * 512 + 256, DDBA, NA);
    }

    // ---- layer 3: fork the two independent chains (small L2 footprint -> safe) ----
    // chain S (side stream): gemm_n16_B -> gat16_A (writes xaOut)
    // chain 0 (main stream): gemm_n16_A -> gat16_B -> sumrows16
    cudaEventRecord(evFork3, 0);
    cudaStreamWaitEvent(s1, evFork3, 0);

    gemm_n16_kernel<<<cdiv(NB, 32), 512, 0, s1>>>(XBH, XBL, Wba[2], HBAf, NB, asba[2], SSBA);
    gat16_kernel<<<cdiv(NA, 8), 256, 0, s1>>>(RP2 + NB, SRT, SSBA, DDBA, HBAf, bba[2], xaOut, NA);
    cudaEventRecord(evL3, s1);

    gemm_n16_kernel<<<cdiv(NA, 32), 512>>>(XAH, XAL, Wab[2], HABf, NA, asab[2], SSAB);
    gat16_kernel<<<cdiv(NB, 8), 256>>>(RP2, SRT, SSAB, DDAB, HABf, bab[2], xbOut, NB);

    cudaMemsetAsync(SUM16, 0, 16 * sizeof(float), 0);
    sumrows16_kernel<<<256, 256>>>(xbOut, dstI, SUM16, LPRED);

    cudaStreamWaitEvent(0, evL3, 0);
    pred_kernel<<<cdiv(LPRED, 256), 256>>>(xaOut, srcI, SUM16, pred, LPRED);
}